// round 7
// baseline (speedup 1.0000x reference)
#include <cuda_runtime.h>
#include <cuda_bf16.h>
#include <cstdint>

#define B_DIM 2
#define T_DIM 4096
#define C_DIM 1024
#define H_DIM 16
#define D_DIM 64
#define MROWS (B_DIM * T_DIM)   // 8192
#define KDIM  C_DIM             // 1024

// ---------------- static device scratch (no allocs allowed) ----------------
__device__ __align__(256) __nv_bfloat16 g_xh[(size_t)MROWS * KDIM];
__device__ __align__(256) __nv_bfloat16 g_xl[(size_t)MROWS * KDIM];
__device__ __align__(256) __nv_bfloat16 g_wqh[(size_t)3 * C_DIM * KDIM];
__device__ __align__(256) __nv_bfloat16 g_wql[(size_t)3 * C_DIM * KDIM];
__device__ __align__(256) __nv_bfloat16 g_woh[(size_t)C_DIM * KDIM];
__device__ __align__(256) __nv_bfloat16 g_wol[(size_t)C_DIM * KDIM];
__device__ __align__(256) __nv_bfloat16 g_ah[(size_t)MROWS * KDIM];
__device__ __align__(256) __nv_bfloat16 g_al[(size_t)MROWS * KDIM];

// per-head [b,h,t,d] bf16 hi/lo for attention
__device__ __align__(256) __nv_bfloat16 g_qh2[(size_t)MROWS * C_DIM];
__device__ __align__(256) __nv_bfloat16 g_ql2[(size_t)MROWS * C_DIM];
__device__ __align__(256) __nv_bfloat16 g_kh2[(size_t)MROWS * C_DIM];
__device__ __align__(256) __nv_bfloat16 g_kl2[(size_t)MROWS * C_DIM];
__device__ __align__(256) __nv_bfloat16 g_vh2[(size_t)MROWS * C_DIM];
__device__ __align__(256) __nv_bfloat16 g_vl2[(size_t)MROWS * C_DIM];

// ---------------------------------------------------------------------------
// PTX helpers
// ---------------------------------------------------------------------------
__device__ __forceinline__ uint32_t cvta_s(const void* p) {
    uint32_t a;
    asm("{ .reg .u64 t; cvta.to.shared.u64 t, %1; cvt.u32.u64 %0, t; }"
        : "=r"(a) : "l"(p));
    return a;
}

__device__ __forceinline__ void cp16(uint32_t dst, const void* src) {
    asm volatile("cp.async.cg.shared.global [%0], [%1], 16;"
                 :: "r"(dst), "l"(src) : "memory");
}

__device__ __forceinline__ void ldm4(uint32_t addr, uint32_t& r0, uint32_t& r1,
                                     uint32_t& r2, uint32_t& r3) {
    asm volatile("ldmatrix.sync.aligned.m8n8.x4.shared.b16 {%0,%1,%2,%3}, [%4];"
                 : "=r"(r0), "=r"(r1), "=r"(r2), "=r"(r3) : "r"(addr));
}

__device__ __forceinline__ void ldm4t(uint32_t addr, uint32_t& r0, uint32_t& r1,
                                      uint32_t& r2, uint32_t& r3) {
    asm volatile("ldmatrix.sync.aligned.m8n8.x4.trans.shared.b16 {%0,%1,%2,%3}, [%4];"
                 : "=r"(r0), "=r"(r1), "=r"(r2), "=r"(r3) : "r"(addr));
}

__device__ __forceinline__ void mma_bf16(float* d, const uint32_t* a,
                                         uint32_t b0, uint32_t b1) {
    asm volatile(
        "mma.sync.aligned.m16n8k16.row.col.f32.bf16.bf16.f32 "
        "{%0,%1,%2,%3}, {%4,%5,%6,%7}, {%8,%9}, {%0,%1,%2,%3};"
        : "+f"(d[0]), "+f"(d[1]), "+f"(d[2]), "+f"(d[3])
        : "r"(a[0]), "r"(a[1]), "r"(a[2]), "r"(a[3]), "r"(b0), "r"(b1));
}

__device__ __forceinline__ float ex2f(float x) {
    float y;
    asm("ex2.approx.f32 %0, %1;" : "=f"(y) : "f"(x));
    return y;
}

__device__ __forceinline__ uint32_t packbf(float lo, float hi) {
    uint32_t r;
    asm("cvt.rn.bf16x2.f32 %0, %1, %2;" : "=r"(r) : "f"(hi), "f"(lo));
    return r;
}
__device__ __forceinline__ uint32_t packres(uint32_t hp, float f0, float f1) {
    float h0 = __uint_as_float(hp << 16);
    float h1 = __uint_as_float(hp & 0xffff0000u);
    return packbf(f0 - h0, f1 - h1);
}

// SW128: row r (128B rows), 16B chunk c(0..7) -> byte offset
__device__ __forceinline__ uint32_t swz(uint32_t r, uint32_t c) {
    return r * 128 + ((c ^ (r & 7)) << 4);
}

// ---------------------------------------------------------------------------
// split fp32 -> bf16 hi + lo
// ---------------------------------------------------------------------------
__global__ __launch_bounds__(256) void split_bf16(
    const float4* __restrict__ in, uint32_t* __restrict__ hi,
    uint32_t* __restrict__ lo, int n4)
{
    int i = blockIdx.x * blockDim.x + threadIdx.x;
    if (i >= n4) return;
    float4 v = in[i];
    uint32_t h0 = packbf(v.x, v.y), h1 = packbf(v.z, v.w);
    hi[2 * i] = h0; hi[2 * i + 1] = h1;
    lo[2 * i] = packres(h0, v.x, v.y);
    lo[2 * i + 1] = packres(h1, v.z, v.w);
}

// ---------------------------------------------------------------------------
// 3-term split-bf16 GEMM, SW128 smem, 3-stage pipeline, term-major MMA order.
// MODE 0: write fp32 C.   MODE 1: write bf16 hi/lo q/k/v in [b,h,t,d].
// ---------------------------------------------------------------------------
#define GTILE   16384
#define GSTAGE  32768
#define GNSTAGE 3

__device__ __forceinline__ void g_ldtile(
    const __nv_bfloat16* __restrict__ Gh, const __nv_bfloat16* __restrict__ Gl,
    int K, int row0, int k0, uint32_t base, int tid)
{
#pragma unroll
    for (int t = 0; t < 4; t++) {
        int idx = tid + t * 256;
        int r = idx >> 3, c = idx & 7;
        const __nv_bfloat16* src = (c < 4)
            ? Gh + (size_t)(row0 + r) * K + k0 + c * 8
            : Gl + (size_t)(row0 + r) * K + k0 + (c - 4) * 8;
        cp16(base + swz(r, c), src);
    }
}

template <int MODE>
__global__ __launch_bounds__(256, 2) void gemm_bf16x3(
    const __nv_bfloat16* __restrict__ Ah, const __nv_bfloat16* __restrict__ Al,
    const __nv_bfloat16* __restrict__ Bh, const __nv_bfloat16* __restrict__ Bl,
    float* __restrict__ C,
    __nv_bfloat16* __restrict__ qh, __nv_bfloat16* __restrict__ ql,
    __nv_bfloat16* __restrict__ kh, __nv_bfloat16* __restrict__ kl,
    __nv_bfloat16* __restrict__ vh, __nv_bfloat16* __restrict__ vl,
    int N, int K)
{
    extern __shared__ __align__(128) char smraw[];
    const uint32_t smbase = cvta_s(smraw);

    const int tid  = threadIdx.x;
    const int wid  = tid >> 5;
    const int lane = tid & 31;
    const int n0 = blockIdx.x * 128;
    const int m0 = blockIdx.y * 128;
    const int wm = (wid & 1) * 64;
    const int wn = (wid >> 1) * 32;
    const int lr = lane & 15;
    const int lc = lane >> 4;

    float acc[4][4][4];
#pragma unroll
    for (int i = 0; i < 4; i++)
#pragma unroll
        for (int j = 0; j < 4; j++)
#pragma unroll
            for (int k = 0; k < 4; k++) acc[i][j][k] = 0.0f;

    const int nch = K / 32;

#pragma unroll
    for (int c = 0; c < 2; c++) {
        uint32_t sb = smbase + c * GSTAGE;
        g_ldtile(Ah, Al, K, m0, c * 32, sb, tid);
        g_ldtile(Bh, Bl, K, n0, c * 32, sb + GTILE, tid);
        asm volatile("cp.async.commit_group;" ::: "memory");
    }

    for (int c = 0; c < nch; c++) {
        if (c + 1 < nch)
            asm volatile("cp.async.wait_group 1;" ::: "memory");
        else
            asm volatile("cp.async.wait_group 0;" ::: "memory");
        __syncthreads();

        if (c + 2 < nch) {
            uint32_t db = smbase + ((c + 2) % GNSTAGE) * GSTAGE;
            int kk = (c + 2) * 32;
            g_ldtile(Ah, Al, K, m0, kk, db, tid);
            g_ldtile(Bh, Bl, K, n0, kk, db + GTILE, tid);
            asm volatile("cp.async.commit_group;" ::: "memory");
        }

        uint32_t sb = smbase + (c % GNSTAGE) * GSTAGE;

#pragma unroll
        for (int ks = 0; ks < 2; ks++) {
            const uint32_t ch = ks * 2 + lc;
            uint32_t ah[4][4], al4[4][4];
#pragma unroll
            for (int mt = 0; mt < 4; mt++) {
                uint32_t row = wm + mt * 16 + lr;
                uint32_t rb = sb + row * 128;
                uint32_t key = row & 7;
                ldm4(rb + ((ch ^ key) << 4),
                     ah[mt][0], ah[mt][1], ah[mt][2], ah[mt][3]);
                ldm4(rb + (((ch + 4) ^ key) << 4),
                     al4[mt][0], al4[mt][1], al4[mt][2], al4[mt][3]);
            }
            uint32_t bh[2][4], bl[2][4];
#pragma unroll
            for (int p = 0; p < 2; p++) {
                uint32_t row = wn + p * 16 + lr;
                uint32_t rb = sb + GTILE + row * 128;
                uint32_t key = row & 7;
                ldm4(rb + ((ch ^ key) << 4),
                     bh[p][0], bh[p][1], bh[p][2], bh[p][3]);
                ldm4(rb + (((ch + 4) ^ key) << 4),
                     bl[p][0], bl[p][1], bl[p][2], bl[p][3]);
            }
            // term-major: each accumulator revisited only after 16 other MMAs
#pragma unroll
            for (int mt = 0; mt < 4; mt++)
#pragma unroll
                for (int nt = 0; nt < 4; nt++) {
                    const int p = nt >> 1, h = nt & 1;
                    mma_bf16(acc[mt][nt], ah[mt], bh[p][h], bh[p][2 + h]);
                }
#pragma unroll
            for (int mt = 0; mt < 4; mt++)
#pragma unroll
                for (int nt = 0; nt < 4; nt++) {
                    const int p = nt >> 1, h = nt & 1;
                    mma_bf16(acc[mt][nt], al4[mt], bh[p][h], bh[p][2 + h]);
                }
#pragma unroll
            for (int mt = 0; mt < 4; mt++)
#pragma unroll
                for (int nt = 0; nt < 4; nt++) {
                    const int p = nt >> 1, h = nt & 1;
                    mma_bf16(acc[mt][nt], ah[mt], bl[p][h], bl[p][2 + h]);
                }
        }
    }

    const int er = lane >> 2;
    const int ec = (lane & 3) * 2;
#pragma unroll
    for (int mt = 0; mt < 4; mt++) {
#pragma unroll
        for (int nt = 0; nt < 4; nt++) {
            if (MODE == 0) {
                size_t row = (size_t)(m0 + wm + mt * 16 + er);
                int col = n0 + wn + nt * 8 + ec;
                *(float2*)(C + row * N + col) =
                    make_float2(acc[mt][nt][0], acc[mt][nt][1]);
                *(float2*)(C + (row + 8) * N + col) =
                    make_float2(acc[mt][nt][2], acc[mt][nt][3]);
            } else {
                int col = n0 + wn + nt * 8 + ec;
                int type = col >> 10;
                int hh = (col >> 6) & 15;
                int d = col & 63;
                __nv_bfloat16* dh = (type == 0) ? qh : (type == 1) ? kh : vh;
                __nv_bfloat16* dl = (type == 0) ? ql : (type == 1) ? kl : vl;
#pragma unroll
                for (int rr = 0; rr < 2; rr++) {
                    int row = m0 + wm + mt * 16 + er + rr * 8;
                    int bb = row >> 12, tt = row & 4095;
                    size_t o = ((size_t)(bb * H_DIM + hh) * T_DIM + tt) * 64 + d;
                    float v0 = acc[mt][nt][2 * rr], v1 = acc[mt][nt][2 * rr + 1];
                    uint32_t hp = packbf(v0, v1);
                    *(uint32_t*)(dh + o) = hp;
                    *(uint32_t*)(dl + o) = packres(hp, v0, v1);
                }
            }
        }
    }
}

// ---------------------------------------------------------------------------
// Flash attention on mma.sync, split-bf16, causal, term-major MMA order.
// Br=128 (8 warps), Bc=64, SW128 smem, 2-stage.
// ---------------------------------------------------------------------------
#define AQT 16384
#define AKT 8192
#define AST 32768
#define ASOFF 32768

__device__ __forceinline__ void kload(
    const __nv_bfloat16* __restrict__ kh, const __nv_bfloat16* __restrict__ kl,
    const __nv_bfloat16* __restrict__ vh, const __nv_bfloat16* __restrict__ vl,
    size_t gbase, uint32_t st, int tid)
{
    const __nv_bfloat16* ptrs[4] = {kh, kl, vh, vl};
#pragma unroll
    for (int t = 0; t < 8; t++) {
        int idx = tid + t * 256;
        int tile = idx >> 9;
        int rem = idx & 511;
        int r = rem >> 3, c = rem & 7;
        cp16(st + tile * AKT + swz(r, c),
             ptrs[tile] + gbase + (size_t)r * 64 + c * 8);
    }
}

__global__ __launch_bounds__(256, 2) void attn_mma(
    const __nv_bfloat16* __restrict__ qh_, const __nv_bfloat16* __restrict__ ql_,
    const __nv_bfloat16* __restrict__ kh_, const __nv_bfloat16* __restrict__ kl_,
    const __nv_bfloat16* __restrict__ vh_, const __nv_bfloat16* __restrict__ vl_,
    __nv_bfloat16* __restrict__ ah_, __nv_bfloat16* __restrict__ al_)
{
    extern __shared__ __align__(128) char smraw2[];
    const uint32_t sb = cvta_s(smraw2);
    const int qt = gridDim.x - 1 - blockIdx.x;
    const int h = blockIdx.y, b = blockIdx.z;
    const int tid = threadIdx.x, warp = tid >> 5, lane = tid & 31;
    const int q0 = qt * 128;
    const size_t head = (size_t)(b * H_DIM + h) * T_DIM;
    const int nkt = 2 * qt + 2;
    const int lr = lane & 15, lc = lane >> 4;

    // ---- prologue: Q (hi/lo) + stage0 ----
    {
        size_t g = (head + q0) * 64;
#pragma unroll
        for (int t = 0; t < 8; t++) {
            int idx = tid + t * 256;
            int tile = idx >> 10;
            int rem = idx & 1023;
            int r = rem >> 3, c = rem & 7;
            cp16(sb + tile * AQT + swz(r, c),
                 (tile ? ql_ : qh_) + g + (size_t)r * 64 + c * 8);
        }
        kload(kh_, kl_, vh_, vl_, head * 64, sb + ASOFF, tid);
        asm volatile("cp.async.commit_group;" ::: "memory");
        asm volatile("cp.async.wait_group 0;" ::: "memory");
    }
    __syncthreads();

    // ---- Q fragments ----
    uint32_t qf[4][4], qg[4][4];
    {
        uint32_t row = warp * 16 + lr;
        uint32_t rb = sb + row * 128;
        uint32_t key = row & 7;
#pragma unroll
        for (int ks = 0; ks < 4; ks++) {
            uint32_t ch = ks * 2 + lc;
            ldm4(rb + ((ch ^ key) << 4),
                 qf[ks][0], qf[ks][1], qf[ks][2], qf[ks][3]);
            ldm4(rb + AQT + ((ch ^ key) << 4),
                 qg[ks][0], qg[ks][1], qg[ks][2], qg[ks][3]);
        }
    }

    float m0 = -1e30f, m1 = -1e30f, l0 = 0.0f, l1 = 0.0f;
    float o[8][4];
#pragma unroll
    for (int i = 0; i < 8; i++)
#pragma unroll
        for (int j = 0; j < 4; j++) o[i][j] = 0.0f;

    const float SC = 0.180336880f;
    const int grow = q0 + warp * 16;

    for (int kt = 0; kt < nkt; kt++) {
        if (kt > 0) {
            asm volatile("cp.async.wait_group 0;" ::: "memory");
            __syncthreads();
        }
        if (kt + 1 < nkt) {
            kload(kh_, kl_, vh_, vl_, (head + (size_t)(kt + 1) * 64) * 64,
                  sb + ASOFF + ((kt + 1) & 1) * AST, tid);
            asm volatile("cp.async.commit_group;" ::: "memory");
        }
        const uint32_t st = sb + ASOFF + (kt & 1) * AST;

        // ---- S = Q K^T (3-term, term-major over ng-pairs) ----
        float s[8][4];
#pragma unroll
        for (int i = 0; i < 8; i++)
#pragma unroll
            for (int j = 0; j < 4; j++) s[i][j] = 0.0f;

#pragma unroll
        for (int ks = 0; ks < 4; ks++) {
            uint32_t ch = ks * 2 + lc;
#pragma unroll
            for (int ngp = 0; ngp < 2; ngp++) {
                uint32_t kh4[2][4], kg4[2][4];
#pragma unroll
                for (int j = 0; j < 2; j++) {
                    uint32_t row = (ngp * 2 + j) * 16 + lr;
                    uint32_t rb = st + row * 128;
                    uint32_t key = row & 7;
                    ldm4(rb + ((ch ^ key) << 4),
                         kh4[j][0], kh4[j][1], kh4[j][2], kh4[j][3]);
                    ldm4(rb + AKT + ((ch ^ key) << 4),
                         kg4[j][0], kg4[j][1], kg4[j][2], kg4[j][3]);
                }
                float* s0 = s[4 * ngp];
                float* s1 = s[4 * ngp + 1];
                float* s2 = s[4 * ngp + 2];
                float* s3 = s[4 * ngp + 3];
                // term hh
                mma_bf16(s0, qf[ks], kh4[0][0], kh4[0][2]);
                mma_bf16(s1, qf[ks], kh4[0][1], kh4[0][3]);
                mma_bf16(s2, qf[ks], kh4[1][0], kh4[1][2]);
                mma_bf16(s3, qf[ks], kh4[1][1], kh4[1][3]);
                // term lh (Q lo x K hi)
                mma_bf16(s0, qg[ks], kh4[0][0], kh4[0][2]);
                mma_bf16(s1, qg[ks], kh4[0][1], kh4[0][3]);
                mma_bf16(s2, qg[ks], kh4[1][0], kh4[1][2]);
                mma_bf16(s3, qg[ks], kh4[1][1], kh4[1][3]);
                // term hl (Q hi x K lo)
                mma_bf16(s0, qf[ks], kg4[0][0], kg4[0][2]);
                mma_bf16(s1, qf[ks], kg4[0][1], kg4[0][3]);
                mma_bf16(s2, qf[ks], kg4[1][0], kg4[1][2]);
                mma_bf16(s3, qf[ks], kg4[1][1], kg4[1][3]);
            }
        }

        // ---- causal mask ----
        if (kt * 64 + 63 > grow) {
            const int rb0 = grow + (lane >> 2);
            const int cb = kt * 64 + (lane & 3) * 2;
#pragma unroll
            for (int nt = 0; nt < 8; nt++) {
                int c0 = cb + nt * 8;
                if (c0     > rb0)     s[nt][0] = -1e30f;
                if (c0 + 1 > rb0)     s[nt][1] = -1e30f;
                if (c0     > rb0 + 8) s[nt][2] = -1e30f;
                if (c0 + 1 > rb0 + 8) s[nt][3] = -1e30f;
            }
        }

        // ---- online softmax (base-2) ----
        float mx0 = s[0][0], mx1 = s[0][2];
#pragma unroll
        for (int nt = 0; nt < 8; nt++) {
            mx0 = fmaxf(mx0, fmaxf(s[nt][0], s[nt][1]));
            mx1 = fmaxf(mx1, fmaxf(s[nt][2], s[nt][3]));
        }
        mx0 = fmaxf(mx0, __shfl_xor_sync(0xffffffffu, mx0, 1));
        mx0 = fmaxf(mx0, __shfl_xor_sync(0xffffffffu, mx0, 2));
        mx1 = fmaxf(mx1, __shfl_xor_sync(0xffffffffu, mx1, 1));
        mx1 = fmaxf(mx1, __shfl_xor_sync(0xffffffffu, mx1, 2));

        float mn0 = fmaxf(m0, mx0), mn1 = fmaxf(m1, mx1);
        float a0 = ex2f((m0 - mn0) * SC), a1 = ex2f((m1 - mn1) * SC);
        m0 = mn0; m1 = mn1;

        float rs0 = 0.0f, rs1 = 0.0f;
#pragma unroll
        for (int nt = 0; nt < 8; nt++) {
            s[nt][0] = ex2f((s[nt][0] - mn0) * SC);
            s[nt][1] = ex2f((s[nt][1] - mn0) * SC);
            s[nt][2] = ex2f((s[nt][2] - mn1) * SC);
            s[nt][3] = ex2f((s[nt][3] - mn1) * SC);
            rs0 += s[nt][0] + s[nt][1];
            rs1 += s[nt][2] + s[nt][3];
        }
        rs0 += __shfl_xor_sync(0xffffffffu, rs0, 1);
        rs0 += __shfl_xor_sync(0xffffffffu, rs0, 2);
        rs1 += __shfl_xor_sync(0xffffffffu, rs1, 1);
        rs1 += __shfl_xor_sync(0xffffffffu, rs1, 2);
        l0 = l0 * a0 + rs0;
        l1 = l1 * a1 + rs1;

#pragma unroll
        for (int i = 0; i < 8; i++) {
            o[i][0] *= a0; o[i][1] *= a0;
            o[i][2] *= a1; o[i][3] *= a1;
        }

        // ---- O += P V (3-term, term-major over dg-pairs) ----
#pragma unroll
        for (int ks2 = 0; ks2 < 4; ks2++) {
            uint32_t pa[4], pb[4];
            pa[0] = packbf(s[2 * ks2][0],     s[2 * ks2][1]);
            pa[1] = packbf(s[2 * ks2][2],     s[2 * ks2][3]);
            pa[2] = packbf(s[2 * ks2 + 1][0], s[2 * ks2 + 1][1]);
            pa[3] = packbf(s[2 * ks2 + 1][2], s[2 * ks2 + 1][3]);
            pb[0] = packres(pa[0], s[2 * ks2][0],     s[2 * ks2][1]);
            pb[1] = packres(pa[1], s[2 * ks2][2],     s[2 * ks2][3]);
            pb[2] = packres(pa[2], s[2 * ks2 + 1][0], s[2 * ks2 + 1][1]);
            pb[3] = packres(pa[3], s[2 * ks2 + 1][2], s[2 * ks2 + 1][3]);

            uint32_t row = ks2 * 16 + lr;
            uint32_t rb = st + 2 * AKT + row * 128;
            uint32_t key = row & 7;
#pragma unroll
            for (int dgp = 0; dgp < 2; dgp++) {
                uint32_t v4[2][4], w4[2][4];
#pragma unroll
                for (int j = 0; j < 2; j++) {
                    uint32_t ch = (dgp * 2 + j) * 2 + lc;
                    uint32_t a = rb + ((ch ^ key) << 4);
                    ldm4t(a, v4[j][0], v4[j][1], v4[j][2], v4[j][3]);
                    ldm4t(a + AKT, w4[j][0], w4[j][1], w4[j][2], w4[j][3]);
                }
                float* o0 = o[4 * dgp];
                float* o1 = o[4 * dgp + 1];
                float* o2 = o[4 * dgp + 2];
                float* o3 = o[4 * dgp + 3];
                // term Ph*Vh
                mma_bf16(o0, pa, v4[0][0], v4[0][1]);
                mma_bf16(o1, pa, v4[0][2], v4[0][3]);
                mma_bf16(o2, pa, v4[1][0], v4[1][1]);
                mma_bf16(o3, pa, v4[1][2], v4[1][3]);
                // term Pl*Vh
                mma_bf16(o0, pb, v4[0][0], v4[0][1]);
                mma_bf16(o1, pb, v4[0][2], v4[0][3]);
                mma_bf16(o2, pb, v4[1][0], v4[1][1]);
                mma_bf16(o3, pb, v4[1][2], v4[1][3]);
                // term Ph*Vl
                mma_bf16(o0, pa, w4[0][0], w4[0][1]);
                mma_bf16(o1, pa, w4[0][2], w4[0][3]);
                mma_bf16(o2, pa, w4[1][0], w4[1][1]);
                mma_bf16(o3, pa, w4[1][2], w4[1][3]);
            }
        }
    }

    // ---- epilogue ----
    const float i0 = 1.0f / l0, i1 = 1.0f / l1;
    const int row = q0 + warp * 16 + (lane >> 2);
    const size_t ob = ((size_t)b * T_DIM + row) * C_DIM + h * 64 + (lane & 3) * 2;
#pragma unroll
    for (int dnt = 0; dnt < 8; dnt++) {
        float v0 = o[dnt][0] * i0, v1 = o[dnt][1] * i0;
        uint32_t hp = packbf(v0, v1);
        *(uint32_t*)(ah_ + ob + dnt * 8) = hp;
        *(uint32_t*)(al_ + ob + dnt * 8) = packres(hp, v0, v1);
        float u0 = o[dnt][2] * i1, u1 = o[dnt][3] * i1;
        uint32_t hq = packbf(u0, u1);
        *(uint32_t*)(ah_ + ob + 8 * C_DIM + dnt * 8) = hq;
        *(uint32_t*)(al_ + ob + 8 * C_DIM + dnt * 8) = packres(hq, u0, u1);
    }
}

// ---------------------------------------------------------------------------
// launch
// ---------------------------------------------------------------------------
extern "C" void kernel_launch(void* const* d_in, const int* in_sizes, int n_in,
                              void* d_out, int out_size)
{
    const float* x    = (const float*)d_in[0];
    const float* wqkv = (const float*)d_in[1];
    const float* wout = (const float*)d_in[2];
    float* out = (float*)d_out;

    __nv_bfloat16 *xh, *xl, *wqh, *wql, *woh, *wol, *ah, *al;
    __nv_bfloat16 *qh2, *ql2, *kh2, *kl2, *vh2, *vl2;
    cudaGetSymbolAddress((void**)&xh, g_xh);
    cudaGetSymbolAddress((void**)&xl, g_xl);
    cudaGetSymbolAddress((void**)&wqh, g_wqh);
    cudaGetSymbolAddress((void**)&wql, g_wql);
    cudaGetSymbolAddress((void**)&woh, g_woh);
    cudaGetSymbolAddress((void**)&wol, g_wol);
    cudaGetSymbolAddress((void**)&ah, g_ah);
    cudaGetSymbolAddress((void**)&al, g_al);
    cudaGetSymbolAddress((void**)&qh2, g_qh2);
    cudaGetSymbolAddress((void**)&ql2, g_ql2);
    cudaGetSymbolAddress((void**)&kh2, g_kh2);
    cudaGetSymbolAddress((void**)&kl2, g_kl2);
    cudaGetSymbolAddress((void**)&vh2, g_vh2);
    cudaGetSymbolAddress((void**)&vl2, g_vl2);

    const int gemm_smem = GNSTAGE * GSTAGE;
    cudaFuncSetAttribute(gemm_bf16x3<0>, cudaFuncAttributeMaxDynamicSharedMemorySize,
                         gemm_smem);
    cudaFuncSetAttribute(gemm_bf16x3<1>, cudaFuncAttributeMaxDynamicSharedMemorySize,
                         gemm_smem);
    const int attn_smem = ASOFF + 2 * AST;
    cudaFuncSetAttribute(attn_mma, cudaFuncAttributeMaxDynamicSharedMemorySize,
                         attn_smem);

    {
        int n4 = MROWS * KDIM / 4;
        split_bf16<<<(n4 + 255) / 256, 256>>>((const float4*)x,
            (uint32_t*)xh, (uint32_t*)xl, n4);
        n4 = 3 * C_DIM * KDIM / 4;
        split_bf16<<<(n4 + 255) / 256, 256>>>((const float4*)wqkv,
            (uint32_t*)wqh, (uint32_t*)wql, n4);
        n4 = C_DIM * KDIM / 4;
        split_bf16<<<(n4 + 255) / 256, 256>>>((const float4*)wout,
            (uint32_t*)woh, (uint32_t*)wol, n4);
    }

    gemm_bf16x3<1><<<dim3(3 * C_DIM / 128, MROWS / 128), 256, gemm_smem>>>(
        xh, xl, wqh, wql, nullptr,
        qh2, ql2, kh2, kl2, vh2, vl2, 3 * C_DIM, KDIM);

    attn_mma<<<dim3(T_DIM / 128, H_DIM, B_DIM), 256, attn_smem>>>(
        qh2, ql2, kh2, kl2, vh2, vl2, ah, al);

    gemm_bf16x3<0><<<dim3(C_DIM / 128, MROWS / 128), 256, gemm_smem>>>(
        ah, al, woh, wol, out,
        nullptr, nullptr, nullptr, nullptr, nullptr, nullptr, C_DIM, KDIM);
}

// round 8
// speedup vs baseline: 1.0620x; 1.0620x over previous
#include <cuda_runtime.h>
#include <cuda_bf16.h>
#include <cstdint>

#define B_DIM 2
#define T_DIM 4096
#define C_DIM 1024
#define H_DIM 16
#define D_DIM 64
#define MROWS (B_DIM * T_DIM)   // 8192
#define KDIM  C_DIM             // 1024

// ---------------- static device scratch (no allocs allowed) ----------------
__device__ __align__(256) __nv_bfloat16 g_xh[(size_t)MROWS * KDIM];
__device__ __align__(256) __nv_bfloat16 g_xl[(size_t)MROWS * KDIM];
__device__ __align__(256) __nv_bfloat16 g_wqh[(size_t)3 * C_DIM * KDIM];
__device__ __align__(256) __nv_bfloat16 g_wql[(size_t)3 * C_DIM * KDIM];
__device__ __align__(256) __nv_bfloat16 g_woh[(size_t)C_DIM * KDIM];
__device__ __align__(256) __nv_bfloat16 g_wol[(size_t)C_DIM * KDIM];
__device__ __align__(256) __nv_bfloat16 g_ah[(size_t)MROWS * KDIM];
__device__ __align__(256) __nv_bfloat16 g_al[(size_t)MROWS * KDIM];

// per-head [b,h,t,d] bf16 hi/lo for attention
__device__ __align__(256) __nv_bfloat16 g_qh2[(size_t)MROWS * C_DIM];
__device__ __align__(256) __nv_bfloat16 g_ql2[(size_t)MROWS * C_DIM];
__device__ __align__(256) __nv_bfloat16 g_kh2[(size_t)MROWS * C_DIM];
__device__ __align__(256) __nv_bfloat16 g_kl2[(size_t)MROWS * C_DIM];
__device__ __align__(256) __nv_bfloat16 g_vh2[(size_t)MROWS * C_DIM];
__device__ __align__(256) __nv_bfloat16 g_vl2[(size_t)MROWS * C_DIM];

// ---------------------------------------------------------------------------
// PTX helpers
// ---------------------------------------------------------------------------
__device__ __forceinline__ uint32_t cvta_s(const void* p) {
    uint32_t a;
    asm("{ .reg .u64 t; cvta.to.shared.u64 t, %1; cvt.u32.u64 %0, t; }"
        : "=r"(a) : "l"(p));
    return a;
}

__device__ __forceinline__ void cp16(uint32_t dst, const void* src) {
    asm volatile("cp.async.cg.shared.global [%0], [%1], 16;"
                 :: "r"(dst), "l"(src) : "memory");
}

__device__ __forceinline__ void ldm4(uint32_t addr, uint32_t& r0, uint32_t& r1,
                                     uint32_t& r2, uint32_t& r3) {
    asm volatile("ldmatrix.sync.aligned.m8n8.x4.shared.b16 {%0,%1,%2,%3}, [%4];"
                 : "=r"(r0), "=r"(r1), "=r"(r2), "=r"(r3) : "r"(addr));
}

__device__ __forceinline__ void ldm4t(uint32_t addr, uint32_t& r0, uint32_t& r1,
                                      uint32_t& r2, uint32_t& r3) {
    asm volatile("ldmatrix.sync.aligned.m8n8.x4.trans.shared.b16 {%0,%1,%2,%3}, [%4];"
                 : "=r"(r0), "=r"(r1), "=r"(r2), "=r"(r3) : "r"(addr));
}

__device__ __forceinline__ void mma_bf16(float* d, const uint32_t* a,
                                         uint32_t b0, uint32_t b1) {
    asm volatile(
        "mma.sync.aligned.m16n8k16.row.col.f32.bf16.bf16.f32 "
        "{%0,%1,%2,%3}, {%4,%5,%6,%7}, {%8,%9}, {%0,%1,%2,%3};"
        : "+f"(d[0]), "+f"(d[1]), "+f"(d[2]), "+f"(d[3])
        : "r"(a[0]), "r"(a[1]), "r"(a[2]), "r"(a[3]), "r"(b0), "r"(b1));
}

__device__ __forceinline__ float ex2f(float x) {
    float y;
    asm("ex2.approx.f32 %0, %1;" : "=f"(y) : "f"(x));
    return y;
}

__device__ __forceinline__ uint32_t packbf(float lo, float hi) {
    uint32_t r;
    asm("cvt.rn.bf16x2.f32 %0, %1, %2;" : "=r"(r) : "f"(hi), "f"(lo));
    return r;
}
__device__ __forceinline__ uint32_t packres(uint32_t hp, float f0, float f1) {
    float h0 = __uint_as_float(hp << 16);
    float h1 = __uint_as_float(hp & 0xffff0000u);
    return packbf(f0 - h0, f1 - h1);
}

// SW128: row r (128B rows), 16B chunk c(0..7) -> byte offset
__device__ __forceinline__ uint32_t swz(uint32_t r, uint32_t c) {
    return r * 128 + ((c ^ (r & 7)) << 4);
}

// ---------------------------------------------------------------------------
// split fp32 -> bf16 hi + lo
// ---------------------------------------------------------------------------
__global__ __launch_bounds__(256) void split_bf16(
    const float4* __restrict__ in, uint32_t* __restrict__ hi,
    uint32_t* __restrict__ lo, int n4)
{
    int i = blockIdx.x * blockDim.x + threadIdx.x;
    if (i >= n4) return;
    float4 v = in[i];
    uint32_t h0 = packbf(v.x, v.y), h1 = packbf(v.z, v.w);
    hi[2 * i] = h0; hi[2 * i + 1] = h1;
    lo[2 * i] = packres(h0, v.x, v.y);
    lo[2 * i + 1] = packres(h1, v.z, v.w);
}

// ---------------------------------------------------------------------------
// 3-term split-bf16 GEMM. 128x128 CTA tile, 4 warps (64x64 each), BK=32,
// SW128 smem, 3-stage, 2 CTAs/SM, 128 threads, no register cap spills.
// MODE 0: write fp32 C.   MODE 1: write bf16 hi/lo q/k/v in [b,h,t,d].
// ---------------------------------------------------------------------------
#define GTILE   16384
#define GSTAGE  32768
#define GNSTAGE 3

__device__ __forceinline__ void g_ldtile(
    const __nv_bfloat16* __restrict__ Gh, const __nv_bfloat16* __restrict__ Gl,
    int K, int row0, int k0, uint32_t base, int tid)
{
#pragma unroll
    for (int t = 0; t < 8; t++) {
        int idx = tid + t * 128;           // 0..1023
        int r = idx >> 3, c = idx & 7;
        const __nv_bfloat16* src = (c < 4)
            ? Gh + (size_t)(row0 + r) * K + k0 + c * 8
            : Gl + (size_t)(row0 + r) * K + k0 + (c - 4) * 8;
        cp16(base + swz(r, c), src);
    }
}

template <int MODE>
__global__ __launch_bounds__(128, 2) void gemm_bf16x3(
    const __nv_bfloat16* __restrict__ Ah, const __nv_bfloat16* __restrict__ Al,
    const __nv_bfloat16* __restrict__ Bh, const __nv_bfloat16* __restrict__ Bl,
    float* __restrict__ C,
    __nv_bfloat16* __restrict__ qh, __nv_bfloat16* __restrict__ ql,
    __nv_bfloat16* __restrict__ kh, __nv_bfloat16* __restrict__ kl,
    __nv_bfloat16* __restrict__ vh, __nv_bfloat16* __restrict__ vl,
    int N, int K)
{
    extern __shared__ __align__(128) char smraw[];
    const uint32_t smbase = cvta_s(smraw);

    const int tid  = threadIdx.x;
    const int wid  = tid >> 5;             // 0..3
    const int lane = tid & 31;
    const int n0 = blockIdx.x * 128;
    const int m0 = blockIdx.y * 128;
    const int wm = (wid & 1) * 64;         // warp M offset
    const int wn = (wid >> 1) * 64;        // warp N offset
    const int lr = lane & 15;
    const int lc = lane >> 4;

    float acc[4][8][4];
#pragma unroll
    for (int i = 0; i < 4; i++)
#pragma unroll
        for (int j = 0; j < 8; j++)
#pragma unroll
            for (int k = 0; k < 4; k++) acc[i][j][k] = 0.0f;

    const int nch = K / 32;

#pragma unroll
    for (int c = 0; c < 2; c++) {
        uint32_t sb = smbase + c * GSTAGE;
        g_ldtile(Ah, Al, K, m0, c * 32, sb, tid);
        g_ldtile(Bh, Bl, K, n0, c * 32, sb + GTILE, tid);
        asm volatile("cp.async.commit_group;" ::: "memory");
    }

    for (int c = 0; c < nch; c++) {
        if (c + 1 < nch)
            asm volatile("cp.async.wait_group 1;" ::: "memory");
        else
            asm volatile("cp.async.wait_group 0;" ::: "memory");
        __syncthreads();

        if (c + 2 < nch) {
            uint32_t db = smbase + ((c + 2) % GNSTAGE) * GSTAGE;
            int kk = (c + 2) * 32;
            g_ldtile(Ah, Al, K, m0, kk, db, tid);
            g_ldtile(Bh, Bl, K, n0, kk, db + GTILE, tid);
            asm volatile("cp.async.commit_group;" ::: "memory");
        }

        uint32_t sb = smbase + (c % GNSTAGE) * GSTAGE;

#pragma unroll
        for (int ks = 0; ks < 2; ks++) {
            const uint32_t ch = ks * 2 + lc;
            uint32_t ah[4][4], al4[4][4];
#pragma unroll
            for (int mt = 0; mt < 4; mt++) {
                uint32_t row = wm + mt * 16 + lr;
                uint32_t rb = sb + row * 128;
                uint32_t key = row & 7;
                ldm4(rb + ((ch ^ key) << 4),
                     ah[mt][0], ah[mt][1], ah[mt][2], ah[mt][3]);
                ldm4(rb + (((ch + 4) ^ key) << 4),
                     al4[mt][0], al4[mt][1], al4[mt][2], al4[mt][3]);
            }
            uint32_t bh[4][4], bl[4][4];
#pragma unroll
            for (int p = 0; p < 4; p++) {
                uint32_t row = wn + p * 16 + lr;
                uint32_t rb = sb + GTILE + row * 128;
                uint32_t key = row & 7;
                ldm4(rb + ((ch ^ key) << 4),
                     bh[p][0], bh[p][1], bh[p][2], bh[p][3]);
                ldm4(rb + (((ch + 4) ^ key) << 4),
                     bl[p][0], bl[p][1], bl[p][2], bl[p][3]);
            }
#pragma unroll
            for (int mt = 0; mt < 4; mt++) {
#pragma unroll
                for (int nt = 0; nt < 8; nt++) {
                    const int p = nt >> 1, h = nt & 1;
                    mma_bf16(acc[mt][nt], ah[mt],  bh[p][h], bh[p][2 + h]);
                    mma_bf16(acc[mt][nt], al4[mt], bh[p][h], bh[p][2 + h]);
                    mma_bf16(acc[mt][nt], ah[mt],  bl[p][h], bl[p][2 + h]);
                }
            }
        }
    }

    const int er = lane >> 2;
    const int ec = (lane & 3) * 2;
#pragma unroll
    for (int mt = 0; mt < 4; mt++) {
#pragma unroll
        for (int nt = 0; nt < 8; nt++) {
            if (MODE == 0) {
                size_t row = (size_t)(m0 + wm + mt * 16 + er);
                int col = n0 + wn + nt * 8 + ec;
                *(float2*)(C + row * N + col) =
                    make_float2(acc[mt][nt][0], acc[mt][nt][1]);
                *(float2*)(C + (row + 8) * N + col) =
                    make_float2(acc[mt][nt][2], acc[mt][nt][3]);
            } else {
                int col = n0 + wn + nt * 8 + ec;
                int type = col >> 10;
                int hh = (col >> 6) & 15;
                int d = col & 63;
                __nv_bfloat16* dh = (type == 0) ? qh : (type == 1) ? kh : vh;
                __nv_bfloat16* dl = (type == 0) ? ql : (type == 1) ? kl : vl;
#pragma unroll
                for (int rr = 0; rr < 2; rr++) {
                    int row = m0 + wm + mt * 16 + er + rr * 8;
                    int bb = row >> 12, tt = row & 4095;
                    size_t o = ((size_t)(bb * H_DIM + hh) * T_DIM + tt) * 64 + d;
                    float v0 = acc[mt][nt][2 * rr], v1 = acc[mt][nt][2 * rr + 1];
                    uint32_t hp = packbf(v0, v1);
                    *(uint32_t*)(dh + o) = hp;
                    *(uint32_t*)(dl + o) = packres(hp, v0, v1);
                }
            }
        }
    }
}

// ---------------------------------------------------------------------------
// Flash attention on mma.sync, split-bf16, causal (identical to R6 best).
// Br=128 (8 warps), Bc=64, SW128 smem, 2-stage, single barrier per iter.
// ---------------------------------------------------------------------------
#define AQT 16384
#define AKT 8192
#define AST 32768
#define ASOFF 32768

__device__ __forceinline__ void kload(
    const __nv_bfloat16* __restrict__ kh, const __nv_bfloat16* __restrict__ kl,
    const __nv_bfloat16* __restrict__ vh, const __nv_bfloat16* __restrict__ vl,
    size_t gbase, uint32_t st, int tid)
{
    const __nv_bfloat16* ptrs[4] = {kh, kl, vh, vl};
#pragma unroll
    for (int t = 0; t < 8; t++) {
        int idx = tid + t * 256;
        int tile = idx >> 9;
        int rem = idx & 511;
        int r = rem >> 3, c = rem & 7;
        cp16(st + tile * AKT + swz(r, c),
             ptrs[tile] + gbase + (size_t)r * 64 + c * 8);
    }
}

__global__ __launch_bounds__(256, 2) void attn_mma(
    const __nv_bfloat16* __restrict__ qh_, const __nv_bfloat16* __restrict__ ql_,
    const __nv_bfloat16* __restrict__ kh_, const __nv_bfloat16* __restrict__ kl_,
    const __nv_bfloat16* __restrict__ vh_, const __nv_bfloat16* __restrict__ vl_,
    __nv_bfloat16* __restrict__ ah_, __nv_bfloat16* __restrict__ al_)
{
    extern __shared__ __align__(128) char smraw2[];
    const uint32_t sb = cvta_s(smraw2);
    const int qt = gridDim.x - 1 - blockIdx.x;
    const int h = blockIdx.y, b = blockIdx.z;
    const int tid = threadIdx.x, warp = tid >> 5, lane = tid & 31;
    const int q0 = qt * 128;
    const size_t head = (size_t)(b * H_DIM + h) * T_DIM;
    const int nkt = 2 * qt + 2;
    const int lr = lane & 15, lc = lane >> 4;

    // ---- prologue: Q (hi/lo) + stage0 ----
    {
        size_t g = (head + q0) * 64;
#pragma unroll
        for (int t = 0; t < 8; t++) {
            int idx = tid + t * 256;
            int tile = idx >> 10;
            int rem = idx & 1023;
            int r = rem >> 3, c = rem & 7;
            cp16(sb + tile * AQT + swz(r, c),
                 (tile ? ql_ : qh_) + g + (size_t)r * 64 + c * 8);
        }
        kload(kh_, kl_, vh_, vl_, head * 64, sb + ASOFF, tid);
        asm volatile("cp.async.commit_group;" ::: "memory");
        asm volatile("cp.async.wait_group 0;" ::: "memory");
    }
    __syncthreads();

    // ---- Q fragments ----
    uint32_t qf[4][4], qg[4][4];
    {
        uint32_t row = warp * 16 + lr;
        uint32_t rb = sb + row * 128;
        uint32_t key = row & 7;
#pragma unroll
        for (int ks = 0; ks < 4; ks++) {
            uint32_t ch = ks * 2 + lc;
            ldm4(rb + ((ch ^ key) << 4),
                 qf[ks][0], qf[ks][1], qf[ks][2], qf[ks][3]);
            ldm4(rb + AQT + ((ch ^ key) << 4),
                 qg[ks][0], qg[ks][1], qg[ks][2], qg[ks][3]);
        }
    }

    float m0 = -1e30f, m1 = -1e30f, l0 = 0.0f, l1 = 0.0f;
    float o[8][4];
#pragma unroll
    for (int i = 0; i < 8; i++)
#pragma unroll
        for (int j = 0; j < 4; j++) o[i][j] = 0.0f;

    const float SC = 0.180336880f;   // 0.125 * log2(e)
    const int grow = q0 + warp * 16;

    for (int kt = 0; kt < nkt; kt++) {
        if (kt > 0) {
            asm volatile("cp.async.wait_group 0;" ::: "memory");
            __syncthreads();
        }
        if (kt + 1 < nkt) {
            kload(kh_, kl_, vh_, vl_, (head + (size_t)(kt + 1) * 64) * 64,
                  sb + ASOFF + ((kt + 1) & 1) * AST, tid);
            asm volatile("cp.async.commit_group;" ::: "memory");
        }
        const uint32_t st = sb + ASOFF + (kt & 1) * AST;

        // ---- S = Q K^T (3-term) ----
        float s[8][4];
#pragma unroll
        for (int i = 0; i < 8; i++)
#pragma unroll
            for (int j = 0; j < 4; j++) s[i][j] = 0.0f;

#pragma unroll
        for (int ks = 0; ks < 4; ks++) {
            uint32_t ch = ks * 2 + lc;
#pragma unroll
            for (int ng = 0; ng < 4; ng++) {
                uint32_t row = ng * 16 + lr;
                uint32_t rb = st + row * 128;
                uint32_t key = row & 7;
                uint32_t h0, h1, h2, h3, g0, g1, g2, g3;
                ldm4(rb + ((ch ^ key) << 4), h0, h1, h2, h3);
                ldm4(rb + AKT + ((ch ^ key) << 4), g0, g1, g2, g3);
                mma_bf16(s[2 * ng],     qf[ks], h0, h2);
                mma_bf16(s[2 * ng],     qg[ks], h0, h2);
                mma_bf16(s[2 * ng],     qf[ks], g0, g2);
                mma_bf16(s[2 * ng + 1], qf[ks], h1, h3);
                mma_bf16(s[2 * ng + 1], qg[ks], h1, h3);
                mma_bf16(s[2 * ng + 1], qf[ks], g1, g3);
            }
        }

        // ---- causal mask ----
        if (kt * 64 + 63 > grow) {
            const int rb0 = grow + (lane >> 2);
            const int cb = kt * 64 + (lane & 3) * 2;
#pragma unroll
            for (int nt = 0; nt < 8; nt++) {
                int c0 = cb + nt * 8;
                if (c0     > rb0)     s[nt][0] = -1e30f;
                if (c0 + 1 > rb0)     s[nt][1] = -1e30f;
                if (c0     > rb0 + 8) s[nt][2] = -1e30f;
                if (c0 + 1 > rb0 + 8) s[nt][3] = -1e30f;
            }
        }

        // ---- online softmax (base-2) ----
        float mx0 = s[0][0], mx1 = s[0][2];
#pragma unroll
        for (int nt = 0; nt < 8; nt++) {
            mx0 = fmaxf(mx0, fmaxf(s[nt][0], s[nt][1]));
            mx1 = fmaxf(mx1, fmaxf(s[nt][2], s[nt][3]));
        }
        mx0 = fmaxf(mx0, __shfl_xor_sync(0xffffffffu, mx0, 1));
        mx0 = fmaxf(mx0, __shfl_xor_sync(0xffffffffu, mx0, 2));
        mx1 = fmaxf(mx1, __shfl_xor_sync(0xffffffffu, mx1, 1));
        mx1 = fmaxf(mx1, __shfl_xor_sync(0xffffffffu, mx1, 2));

        float mn0 = fmaxf(m0, mx0), mn1 = fmaxf(m1, mx1);
        float a0 = ex2f((m0 - mn0) * SC), a1 = ex2f((m1 - mn1) * SC);
        m0 = mn0; m1 = mn1;

        float rs0 = 0.0f, rs1 = 0.0f;
#pragma unroll
        for (int nt = 0; nt < 8; nt++) {
            s[nt][0] = ex2f((s[nt][0] - mn0) * SC);
            s[nt][1] = ex2f((s[nt][1] - mn0) * SC);
            s[nt][2] = ex2f((s[nt][2] - mn1) * SC);
            s[nt][3] = ex2f((s[nt][3] - mn1) * SC);
            rs0 += s[nt][0] + s[nt][1];
            rs1 += s[nt][2] + s[nt][3];
        }
        rs0 += __shfl_xor_sync(0xffffffffu, rs0, 1);
        rs0 += __shfl_xor_sync(0xffffffffu, rs0, 2);
        rs1 += __shfl_xor_sync(0xffffffffu, rs1, 1);
        rs1 += __shfl_xor_sync(0xffffffffu, rs1, 2);
        l0 = l0 * a0 + rs0;
        l1 = l1 * a1 + rs1;

#pragma unroll
        for (int i = 0; i < 8; i++) {
            o[i][0] *= a0; o[i][1] *= a0;
            o[i][2] *= a1; o[i][3] *= a1;
        }

        // ---- O += P V (3-term) ----
#pragma unroll
        for (int ks2 = 0; ks2 < 4; ks2++) {
            uint32_t pa[4], pb[4];
            pa[0] = packbf(s[2 * ks2][0],     s[2 * ks2][1]);
            pa[1] = packbf(s[2 * ks2][2],     s[2 * ks2][3]);
            pa[2] = packbf(s[2 * ks2 + 1][0], s[2 * ks2 + 1][1]);
            pa[3] = packbf(s[2 * ks2 + 1][2], s[2 * ks2 + 1][3]);
            pb[0] = packres(pa[0], s[2 * ks2][0],     s[2 * ks2][1]);
            pb[1] = packres(pa[1], s[2 * ks2][2],     s[2 * ks2][3]);
            pb[2] = packres(pa[2], s[2 * ks2 + 1][0], s[2 * ks2 + 1][1]);
            pb[3] = packres(pa[3], s[2 * ks2 + 1][2], s[2 * ks2 + 1][3]);

            uint32_t row = ks2 * 16 + lr;
            uint32_t rb = st + 2 * AKT + row * 128;
            uint32_t key = row & 7;
#pragma unroll
            for (int dg = 0; dg < 4; dg++) {
                uint32_t ch = dg * 2 + lc;
                uint32_t a = rb + ((ch ^ key) << 4);
                uint32_t v0, v1, v2, v3, w0, w1, w2, w3;
                ldm4t(a, v0, v1, v2, v3);
                ldm4t(a + AKT, w0, w1, w2, w3);
                mma_bf16(o[2 * dg],     pa, v0, v1);
                mma_bf16(o[2 * dg],     pb, v0, v1);
                mma_bf16(o[2 * dg],     pa, w0, w1);
                mma_bf16(o[2 * dg + 1], pa, v2, v3);
                mma_bf16(o[2 * dg + 1], pb, v2, v3);
                mma_bf16(o[2 * dg + 1], pa, w2, w3);
            }
        }
    }

    // ---- epilogue: normalize, write bf16 hi/lo [b,t,C] ----
    const float i0 = 1.0f / l0, i1 = 1.0f / l1;
    const int row = q0 + warp * 16 + (lane >> 2);
    const size_t ob = ((size_t)b * T_DIM + row) * C_DIM + h * 64 + (lane & 3) * 2;
#pragma unroll
    for (int dnt = 0; dnt < 8; dnt++) {
        float v0 = o[dnt][0] * i0, v1 = o[dnt][1] * i0;
        uint32_t hp = packbf(v0, v1);
        *(uint32_t*)(ah_ + ob + dnt * 8) = hp;
        *(uint32_t*)(al_ + ob + dnt * 8) = packres(hp, v0, v1);
        float u0 = o[dnt][2] * i1, u1 = o[dnt][3] * i1;
        uint32_t hq = packbf(u0, u1);
        *(uint32_t*)(ah_ + ob + 8 * C_DIM + dnt * 8) = hq;
        *(uint32_t*)(al_ + ob + 8 * C_DIM + dnt * 8) = packres(hq, u0, u1);
    }
}

// ---------------------------------------------------------------------------
// launch
// ---------------------------------------------------------------------------
extern "C" void kernel_launch(void* const* d_in, const int* in_sizes, int n_in,
                              void* d_out, int out_size)
{
    const float* x    = (const float*)d_in[0];
    const float* wqkv = (const float*)d_in[1];
    const float* wout = (const float*)d_in[2];
    float* out = (float*)d_out;

    __nv_bfloat16 *xh, *xl, *wqh, *wql, *woh, *wol, *ah, *al;
    __nv_bfloat16 *qh2, *ql2, *kh2, *kl2, *vh2, *vl2;
    cudaGetSymbolAddress((void**)&xh, g_xh);
    cudaGetSymbolAddress((void**)&xl, g_xl);
    cudaGetSymbolAddress((void**)&wqh, g_wqh);
    cudaGetSymbolAddress((void**)&wql, g_wql);
    cudaGetSymbolAddress((void**)&woh, g_woh);
    cudaGetSymbolAddress((void**)&wol, g_wol);
    cudaGetSymbolAddress((void**)&ah, g_ah);
    cudaGetSymbolAddress((void**)&al, g_al);
    cudaGetSymbolAddress((void**)&qh2, g_qh2);
    cudaGetSymbolAddress((void**)&ql2, g_ql2);
    cudaGetSymbolAddress((void**)&kh2, g_kh2);
    cudaGetSymbolAddress((void**)&kl2, g_kl2);
    cudaGetSymbolAddress((void**)&vh2, g_vh2);
    cudaGetSymbolAddress((void**)&vl2, g_vl2);

    const int gemm_smem = GNSTAGE * GSTAGE;     // 98304
    cudaFuncSetAttribute(gemm_bf16x3<0>, cudaFuncAttributeMaxDynamicSharedMemorySize,
                         gemm_smem);
    cudaFuncSetAttribute(gemm_bf16x3<1>, cudaFuncAttributeMaxDynamicSharedMemorySize,
                         gemm_smem);
    const int attn_smem = ASOFF + 2 * AST;      // 98304
    cudaFuncSetAttribute(attn_mma, cudaFuncAttributeMaxDynamicSharedMemorySize,
                         attn_smem);

    {
        int n4 = MROWS * KDIM / 4;
        split_bf16<<<(n4 + 255) / 256, 256>>>((const float4*)x,
            (uint32_t*)xh, (uint32_t*)xl, n4);
        n4 = 3 * C_DIM * KDIM / 4;
        split_bf16<<<(n4 + 255) / 256, 256>>>((const float4*)wqkv,
            (uint32_t*)wqh, (uint32_t*)wql, n4);
        n4 = C_DIM * KDIM / 4;
        split_bf16<<<(n4 + 255) / 256, 256>>>((const float4*)wout,
            (uint32_t*)woh, (uint32_t*)wol, n4);
    }

    // 1) QKV projection, fused split epilogue -> q/k/v hi/lo [b,h,t,d]
    gemm_bf16x3<1><<<dim3(3 * C_DIM / 128, MROWS / 128), 128, gemm_smem>>>(
        xh, xl, wqh, wql, nullptr,
        qh2, ql2, kh2, kl2, vh2, vl2, 3 * C_DIM, KDIM);

    // 2) flash attention (tensor-core), writes bf16 hi/lo att
    attn_mma<<<dim3(T_DIM / 128, H_DIM, B_DIM), 256, attn_smem>>>(
        qh2, ql2, kh2, kl2, vh2, vl2, ah, al);

    // 3) output projection: [8192, 1024] fp32
    gemm_bf16x3<0><<<dim3(C_DIM / 128, MROWS / 128), 128, gemm_smem>>>(
        ah, al, woh, wol, out,
        nullptr, nullptr, nullptr, nullptr, nullptr, nullptr, C_DIM, KDIM);
}

// round 9
// speedup vs baseline: 1.0748x; 1.0120x over previous
#include <cuda_runtime.h>
#include <cuda_bf16.h>
#include <cstdint>

#define B_DIM 2
#define T_DIM 4096
#define C_DIM 1024
#define H_DIM 16
#define D_DIM 64
#define MROWS (B_DIM * T_DIM)   // 8192
#define KDIM  C_DIM             // 1024

// ---------------- static device scratch (no allocs allowed) ----------------
__device__ __align__(256) __nv_bfloat16 g_xh[(size_t)MROWS * KDIM];
__device__ __align__(256) __nv_bfloat16 g_xl[(size_t)MROWS * KDIM];
__device__ __align__(256) __nv_bfloat16 g_wqh[(size_t)3 * C_DIM * KDIM];
__device__ __align__(256) __nv_bfloat16 g_wql[(size_t)3 * C_DIM * KDIM];
__device__ __align__(256) __nv_bfloat16 g_woh[(size_t)C_DIM * KDIM];
__device__ __align__(256) __nv_bfloat16 g_wol[(size_t)C_DIM * KDIM];
__device__ __align__(256) __nv_bfloat16 g_ah[(size_t)MROWS * KDIM];
__device__ __align__(256) __nv_bfloat16 g_al[(size_t)MROWS * KDIM];

// per-head [b,h,t,d] bf16 hi/lo for attention
__device__ __align__(256) __nv_bfloat16 g_qh2[(size_t)MROWS * C_DIM];
__device__ __align__(256) __nv_bfloat16 g_ql2[(size_t)MROWS * C_DIM];
__device__ __align__(256) __nv_bfloat16 g_kh2[(size_t)MROWS * C_DIM];
__device__ __align__(256) __nv_bfloat16 g_kl2[(size_t)MROWS * C_DIM];
__device__ __align__(256) __nv_bfloat16 g_vh2[(size_t)MROWS * C_DIM];
__device__ __align__(256) __nv_bfloat16 g_vl2[(size_t)MROWS * C_DIM];

// ---------------------------------------------------------------------------
// PTX helpers
// ---------------------------------------------------------------------------
__device__ __forceinline__ uint32_t cvta_s(const void* p) {
    uint32_t a;
    asm("{ .reg .u64 t; cvta.to.shared.u64 t, %1; cvt.u32.u64 %0, t; }"
        : "=r"(a) : "l"(p));
    return a;
}

__device__ __forceinline__ void cp16(uint32_t dst, const void* src) {
    asm volatile("cp.async.cg.shared.global [%0], [%1], 16;"
                 :: "r"(dst), "l"(src) : "memory");
}

__device__ __forceinline__ void ldm4(uint32_t addr, uint32_t& r0, uint32_t& r1,
                                     uint32_t& r2, uint32_t& r3) {
    asm volatile("ldmatrix.sync.aligned.m8n8.x4.shared.b16 {%0,%1,%2,%3}, [%4];"
                 : "=r"(r0), "=r"(r1), "=r"(r2), "=r"(r3) : "r"(addr));
}

__device__ __forceinline__ void ldm4t(uint32_t addr, uint32_t& r0, uint32_t& r1,
                                      uint32_t& r2, uint32_t& r3) {
    asm volatile("ldmatrix.sync.aligned.m8n8.x4.trans.shared.b16 {%0,%1,%2,%3}, [%4];"
                 : "=r"(r0), "=r"(r1), "=r"(r2), "=r"(r3) : "r"(addr));
}

__device__ __forceinline__ void mma_bf16(float* d, const uint32_t* a,
                                         uint32_t b0, uint32_t b1) {
    asm volatile(
        "mma.sync.aligned.m16n8k16.row.col.f32.bf16.bf16.f32 "
        "{%0,%1,%2,%3}, {%4,%5,%6,%7}, {%8,%9}, {%0,%1,%2,%3};"
        : "+f"(d[0]), "+f"(d[1]), "+f"(d[2]), "+f"(d[3])
        : "r"(a[0]), "r"(a[1]), "r"(a[2]), "r"(a[3]), "r"(b0), "r"(b1));
}

__device__ __forceinline__ float ex2f(float x) {
    float y;
    asm("ex2.approx.f32 %0, %1;" : "=f"(y) : "f"(x));
    return y;
}

__device__ __forceinline__ uint32_t packbf(float lo, float hi) {
    uint32_t r;
    asm("cvt.rn.bf16x2.f32 %0, %1, %2;" : "=r"(r) : "f"(hi), "f"(lo));
    return r;
}
__device__ __forceinline__ uint32_t packres(uint32_t hp, float f0, float f1) {
    float h0 = __uint_as_float(hp << 16);
    float h1 = __uint_as_float(hp & 0xffff0000u);
    return packbf(f0 - h0, f1 - h1);
}

// SW128: row r (128B rows), 16B chunk c(0..7) -> byte offset
__device__ __forceinline__ uint32_t swz(uint32_t r, uint32_t c) {
    return r * 128 + ((c ^ (r & 7)) << 4);
}

// ---------------------------------------------------------------------------
// split fp32 -> bf16 hi + lo
// ---------------------------------------------------------------------------
__global__ __launch_bounds__(256) void split_bf16(
    const float4* __restrict__ in, uint32_t* __restrict__ hi,
    uint32_t* __restrict__ lo, int n4)
{
    int i = blockIdx.x * blockDim.x + threadIdx.x;
    if (i >= n4) return;
    float4 v = in[i];
    uint32_t h0 = packbf(v.x, v.y), h1 = packbf(v.z, v.w);
    hi[2 * i] = h0; hi[2 * i + 1] = h1;
    lo[2 * i] = packres(h0, v.x, v.y);
    lo[2 * i + 1] = packres(h1, v.z, v.w);
}

// ---------------------------------------------------------------------------
// 3-term split-bf16 GEMM (identical to R8 best).
// ---------------------------------------------------------------------------
#define GTILE   16384
#define GSTAGE  32768
#define GNSTAGE 3

__device__ __forceinline__ void g_ldtile(
    const __nv_bfloat16* __restrict__ Gh, const __nv_bfloat16* __restrict__ Gl,
    int K, int row0, int k0, uint32_t base, int tid)
{
#pragma unroll
    for (int t = 0; t < 8; t++) {
        int idx = tid + t * 128;
        int r = idx >> 3, c = idx & 7;
        const __nv_bfloat16* src = (c < 4)
            ? Gh + (size_t)(row0 + r) * K + k0 + c * 8
            : Gl + (size_t)(row0 + r) * K + k0 + (c - 4) * 8;
        cp16(base + swz(r, c), src);
    }
}

template <int MODE>
__global__ __launch_bounds__(128, 2) void gemm_bf16x3(
    const __nv_bfloat16* __restrict__ Ah, const __nv_bfloat16* __restrict__ Al,
    const __nv_bfloat16* __restrict__ Bh, const __nv_bfloat16* __restrict__ Bl,
    float* __restrict__ C,
    __nv_bfloat16* __restrict__ qh, __nv_bfloat16* __restrict__ ql,
    __nv_bfloat16* __restrict__ kh, __nv_bfloat16* __restrict__ kl,
    __nv_bfloat16* __restrict__ vh, __nv_bfloat16* __restrict__ vl,
    int N, int K)
{
    extern __shared__ __align__(128) char smraw[];
    const uint32_t smbase = cvta_s(smraw);

    const int tid  = threadIdx.x;
    const int wid  = tid >> 5;
    const int lane = tid & 31;
    const int n0 = blockIdx.x * 128;
    const int m0 = blockIdx.y * 128;
    const int wm = (wid & 1) * 64;
    const int wn = (wid >> 1) * 64;
    const int lr = lane & 15;
    const int lc = lane >> 4;

    float acc[4][8][4];
#pragma unroll
    for (int i = 0; i < 4; i++)
#pragma unroll
        for (int j = 0; j < 8; j++)
#pragma unroll
            for (int k = 0; k < 4; k++) acc[i][j][k] = 0.0f;

    const int nch = K / 32;

#pragma unroll
    for (int c = 0; c < 2; c++) {
        uint32_t sb = smbase + c * GSTAGE;
        g_ldtile(Ah, Al, K, m0, c * 32, sb, tid);
        g_ldtile(Bh, Bl, K, n0, c * 32, sb + GTILE, tid);
        asm volatile("cp.async.commit_group;" ::: "memory");
    }

    for (int c = 0; c < nch; c++) {
        if (c + 1 < nch)
            asm volatile("cp.async.wait_group 1;" ::: "memory");
        else
            asm volatile("cp.async.wait_group 0;" ::: "memory");
        __syncthreads();

        if (c + 2 < nch) {
            uint32_t db = smbase + ((c + 2) % GNSTAGE) * GSTAGE;
            int kk = (c + 2) * 32;
            g_ldtile(Ah, Al, K, m0, kk, db, tid);
            g_ldtile(Bh, Bl, K, n0, kk, db + GTILE, tid);
            asm volatile("cp.async.commit_group;" ::: "memory");
        }

        uint32_t sb = smbase + (c % GNSTAGE) * GSTAGE;

#pragma unroll
        for (int ks = 0; ks < 2; ks++) {
            const uint32_t ch = ks * 2 + lc;
            uint32_t ah[4][4], al4[4][4];
#pragma unroll
            for (int mt = 0; mt < 4; mt++) {
                uint32_t row = wm + mt * 16 + lr;
                uint32_t rb = sb + row * 128;
                uint32_t key = row & 7;
                ldm4(rb + ((ch ^ key) << 4),
                     ah[mt][0], ah[mt][1], ah[mt][2], ah[mt][3]);
                ldm4(rb + (((ch + 4) ^ key) << 4),
                     al4[mt][0], al4[mt][1], al4[mt][2], al4[mt][3]);
            }
            uint32_t bh[4][4], bl[4][4];
#pragma unroll
            for (int p = 0; p < 4; p++) {
                uint32_t row = wn + p * 16 + lr;
                uint32_t rb = sb + GTILE + row * 128;
                uint32_t key = row & 7;
                ldm4(rb + ((ch ^ key) << 4),
                     bh[p][0], bh[p][1], bh[p][2], bh[p][3]);
                ldm4(rb + (((ch + 4) ^ key) << 4),
                     bl[p][0], bl[p][1], bl[p][2], bl[p][3]);
            }
#pragma unroll
            for (int mt = 0; mt < 4; mt++) {
#pragma unroll
                for (int nt = 0; nt < 8; nt++) {
                    const int p = nt >> 1, h = nt & 1;
                    mma_bf16(acc[mt][nt], ah[mt],  bh[p][h], bh[p][2 + h]);
                    mma_bf16(acc[mt][nt], al4[mt], bh[p][h], bh[p][2 + h]);
                    mma_bf16(acc[mt][nt], ah[mt],  bl[p][h], bl[p][2 + h]);
                }
            }
        }
    }

    const int er = lane >> 2;
    const int ec = (lane & 3) * 2;
#pragma unroll
    for (int mt = 0; mt < 4; mt++) {
#pragma unroll
        for (int nt = 0; nt < 8; nt++) {
            if (MODE == 0) {
                size_t row = (size_t)(m0 + wm + mt * 16 + er);
                int col = n0 + wn + nt * 8 + ec;
                *(float2*)(C + row * N + col) =
                    make_float2(acc[mt][nt][0], acc[mt][nt][1]);
                *(float2*)(C + (row + 8) * N + col) =
                    make_float2(acc[mt][nt][2], acc[mt][nt][3]);
            } else {
                int col = n0 + wn + nt * 8 + ec;
                int type = col >> 10;
                int hh = (col >> 6) & 15;
                int d = col & 63;
                __nv_bfloat16* dh = (type == 0) ? qh : (type == 1) ? kh : vh;
                __nv_bfloat16* dl = (type == 0) ? ql : (type == 1) ? kl : vl;
#pragma unroll
                for (int rr = 0; rr < 2; rr++) {
                    int row = m0 + wm + mt * 16 + er + rr * 8;
                    int bb = row >> 12, tt = row & 4095;
                    size_t o = ((size_t)(bb * H_DIM + hh) * T_DIM + tt) * 64 + d;
                    float v0 = acc[mt][nt][2 * rr], v1 = acc[mt][nt][2 * rr + 1];
                    uint32_t hp = packbf(v0, v1);
                    *(uint32_t*)(dh + o) = hp;
                    *(uint32_t*)(dl + o) = packres(hp, v0, v1);
                }
            }
        }
    }
}

// ---------------------------------------------------------------------------
// Flash attention v4: 4 warps x 32 rows (Br=128), Bc=64, split-bf16 3-term,
// SW128 smem, 2-stage, 128 threads, 2 CTAs/SM, 255-reg budget.
// ---------------------------------------------------------------------------
#define AQT 16384
#define AKT 8192
#define AST 32768
#define ASOFF 32768

__device__ __forceinline__ void kload(
    const __nv_bfloat16* __restrict__ kh, const __nv_bfloat16* __restrict__ kl,
    const __nv_bfloat16* __restrict__ vh, const __nv_bfloat16* __restrict__ vl,
    size_t gbase, uint32_t st, int tid)
{
    const __nv_bfloat16* ptrs[4] = {kh, kl, vh, vl};
#pragma unroll
    for (int t = 0; t < 16; t++) {
        int idx = tid + t * 128;            // 0..2047
        int tile = idx >> 9;
        int rem = idx & 511;
        int r = rem >> 3, c = rem & 7;
        cp16(st + tile * AKT + swz(r, c),
             ptrs[tile] + gbase + (size_t)r * 64 + c * 8);
    }
}

__global__ __launch_bounds__(128, 2) void attn_mma(
    const __nv_bfloat16* __restrict__ qh_, const __nv_bfloat16* __restrict__ ql_,
    const __nv_bfloat16* __restrict__ kh_, const __nv_bfloat16* __restrict__ kl_,
    const __nv_bfloat16* __restrict__ vh_, const __nv_bfloat16* __restrict__ vl_,
    __nv_bfloat16* __restrict__ ah_, __nv_bfloat16* __restrict__ al_)
{
    extern __shared__ __align__(128) char smraw2[];
    const uint32_t sb = cvta_s(smraw2);
    const int qt = gridDim.x - 1 - blockIdx.x;   // heavy tiles first
    const int h = blockIdx.y, b = blockIdx.z;
    const int tid = threadIdx.x, warp = tid >> 5, lane = tid & 31;
    const int q0 = qt * 128;
    const size_t head = (size_t)(b * H_DIM + h) * T_DIM;
    const int nkt = 2 * qt + 2;
    const int lr = lane & 15, lc = lane >> 4;

    // ---- prologue: Q (hi/lo) + stage0 ----
    {
        size_t g = (head + q0) * 64;
#pragma unroll
        for (int t = 0; t < 16; t++) {
            int idx = tid + t * 128;        // 0..2047
            int tile = idx >> 10;           // 0=hi 1=lo
            int rem = idx & 1023;
            int r = rem >> 3, c = rem & 7;
            cp16(sb + tile * AQT + swz(r, c),
                 (tile ? ql_ : qh_) + g + (size_t)r * 64 + c * 8);
        }
        kload(kh_, kl_, vh_, vl_, head * 64, sb + ASOFF, tid);
        asm volatile("cp.async.commit_group;" ::: "memory");
        asm volatile("cp.async.wait_group 0;" ::: "memory");
    }
    __syncthreads();

    // ---- Q hi fragments, resident (2 m-blocks x 4 ks) ----
    uint32_t qf[2][4][4];
#pragma unroll
    for (int mb = 0; mb < 2; mb++) {
        uint32_t row = warp * 32 + mb * 16 + lr;
        uint32_t rb = sb + row * 128;
        uint32_t key = row & 7;
#pragma unroll
        for (int ks = 0; ks < 4; ks++) {
            uint32_t ch = ks * 2 + lc;
            ldm4(rb + ((ch ^ key) << 4),
                 qf[mb][ks][0], qf[mb][ks][1], qf[mb][ks][2], qf[mb][ks][3]);
        }
    }

    float m[2][2], l[2][2];
#pragma unroll
    for (int mb = 0; mb < 2; mb++) {
        m[mb][0] = -1e30f; m[mb][1] = -1e30f;
        l[mb][0] = 0.0f;   l[mb][1] = 0.0f;
    }
    float o[2][8][4];
#pragma unroll
    for (int mb = 0; mb < 2; mb++)
#pragma unroll
        for (int i = 0; i < 8; i++)
#pragma unroll
            for (int j = 0; j < 4; j++) o[mb][i][j] = 0.0f;

    const float SC = 0.180336880f;   // 0.125 * log2(e)
    const int grow = q0 + warp * 32;

    for (int kt = 0; kt < nkt; kt++) {
        if (kt > 0) {
            asm volatile("cp.async.wait_group 0;" ::: "memory");
            __syncthreads();
        }
        if (kt + 1 < nkt) {
            kload(kh_, kl_, vh_, vl_, (head + (size_t)(kt + 1) * 64) * 64,
                  sb + ASOFF + ((kt + 1) & 1) * AST, tid);
            asm volatile("cp.async.commit_group;" ::: "memory");
        }
        const uint32_t st = sb + ASOFF + (kt & 1) * AST;

        // ---- S = Q K^T (3-term), 2 m-blocks per K fragment ----
        float s[2][8][4];
#pragma unroll
        for (int mb = 0; mb < 2; mb++)
#pragma unroll
            for (int i = 0; i < 8; i++)
#pragma unroll
                for (int j = 0; j < 4; j++) s[mb][i][j] = 0.0f;

#pragma unroll
        for (int ks = 0; ks < 4; ks++) {
            uint32_t ch = ks * 2 + lc;
            uint32_t qg2[2][4];
#pragma unroll
            for (int mb = 0; mb < 2; mb++) {
                uint32_t row = warp * 32 + mb * 16 + lr;
                uint32_t rb = sb + AQT + row * 128;
                uint32_t key = row & 7;
                ldm4(rb + ((ch ^ key) << 4),
                     qg2[mb][0], qg2[mb][1], qg2[mb][2], qg2[mb][3]);
            }
#pragma unroll
            for (int ng = 0; ng < 4; ng++) {
                uint32_t row = ng * 16 + lr;
                uint32_t rb = st + row * 128;
                uint32_t key = row & 7;
                uint32_t h0, h1, h2, h3, g0, g1, g2, g3;
                ldm4(rb + ((ch ^ key) << 4), h0, h1, h2, h3);
                ldm4(rb + AKT + ((ch ^ key) << 4), g0, g1, g2, g3);
#pragma unroll
                for (int mb = 0; mb < 2; mb++) {
                    mma_bf16(s[mb][2 * ng],     qf[mb][ks], h0, h2);
                    mma_bf16(s[mb][2 * ng],     qg2[mb],    h0, h2);
                    mma_bf16(s[mb][2 * ng],     qf[mb][ks], g0, g2);
                    mma_bf16(s[mb][2 * ng + 1], qf[mb][ks], h1, h3);
                    mma_bf16(s[mb][2 * ng + 1], qg2[mb],    h1, h3);
                    mma_bf16(s[mb][2 * ng + 1], qf[mb][ks], g1, g3);
                }
            }
        }

        // ---- causal mask ----
        if (kt * 64 + 63 > grow) {
            const int cb = kt * 64 + (lane & 3) * 2;
#pragma unroll
            for (int mb = 0; mb < 2; mb++) {
                const int rb0 = grow + mb * 16 + (lane >> 2);
#pragma unroll
                for (int nt = 0; nt < 8; nt++) {
                    int c0 = cb + nt * 8;
                    if (c0     > rb0)     s[mb][nt][0] = -1e30f;
                    if (c0 + 1 > rb0)     s[mb][nt][1] = -1e30f;
                    if (c0     > rb0 + 8) s[mb][nt][2] = -1e30f;
                    if (c0 + 1 > rb0 + 8) s[mb][nt][3] = -1e30f;
                }
            }
        }

        // ---- online softmax (base-2), per m-block ----
#pragma unroll
        for (int mb = 0; mb < 2; mb++) {
            float mx0 = s[mb][0][0], mx1 = s[mb][0][2];
#pragma unroll
            for (int nt = 0; nt < 8; nt++) {
                mx0 = fmaxf(mx0, fmaxf(s[mb][nt][0], s[mb][nt][1]));
                mx1 = fmaxf(mx1, fmaxf(s[mb][nt][2], s[mb][nt][3]));
            }
            mx0 = fmaxf(mx0, __shfl_xor_sync(0xffffffffu, mx0, 1));
            mx0 = fmaxf(mx0, __shfl_xor_sync(0xffffffffu, mx0, 2));
            mx1 = fmaxf(mx1, __shfl_xor_sync(0xffffffffu, mx1, 1));
            mx1 = fmaxf(mx1, __shfl_xor_sync(0xffffffffu, mx1, 2));

            float mn0 = fmaxf(m[mb][0], mx0), mn1 = fmaxf(m[mb][1], mx1);
            float a0 = ex2f((m[mb][0] - mn0) * SC);
            float a1 = ex2f((m[mb][1] - mn1) * SC);
            m[mb][0] = mn0; m[mb][1] = mn1;

            float rs0 = 0.0f, rs1 = 0.0f;
#pragma unroll
            for (int nt = 0; nt < 8; nt++) {
                s[mb][nt][0] = ex2f((s[mb][nt][0] - mn0) * SC);
                s[mb][nt][1] = ex2f((s[mb][nt][1] - mn0) * SC);
                s[mb][nt][2] = ex2f((s[mb][nt][2] - mn1) * SC);
                s[mb][nt][3] = ex2f((s[mb][nt][3] - mn1) * SC);
                rs0 += s[mb][nt][0] + s[mb][nt][1];
                rs1 += s[mb][nt][2] + s[mb][nt][3];
            }
            rs0 += __shfl_xor_sync(0xffffffffu, rs0, 1);
            rs0 += __shfl_xor_sync(0xffffffffu, rs0, 2);
            rs1 += __shfl_xor_sync(0xffffffffu, rs1, 1);
            rs1 += __shfl_xor_sync(0xffffffffu, rs1, 2);
            l[mb][0] = l[mb][0] * a0 + rs0;
            l[mb][1] = l[mb][1] * a1 + rs1;

#pragma unroll
            for (int i = 0; i < 8; i++) {
                o[mb][i][0] *= a0; o[mb][i][1] *= a0;
                o[mb][i][2] *= a1; o[mb][i][3] *= a1;
            }
        }

        // ---- O += P V (3-term), 2 m-blocks per V fragment ----
#pragma unroll
        for (int ks2 = 0; ks2 < 4; ks2++) {
            uint32_t pa[2][4], pb[2][4];
#pragma unroll
            for (int mb = 0; mb < 2; mb++) {
                pa[mb][0] = packbf(s[mb][2 * ks2][0],     s[mb][2 * ks2][1]);
                pa[mb][1] = packbf(s[mb][2 * ks2][2],     s[mb][2 * ks2][3]);
                pa[mb][2] = packbf(s[mb][2 * ks2 + 1][0], s[mb][2 * ks2 + 1][1]);
                pa[mb][3] = packbf(s[mb][2 * ks2 + 1][2], s[mb][2 * ks2 + 1][3]);
                pb[mb][0] = packres(pa[mb][0], s[mb][2 * ks2][0],     s[mb][2 * ks2][1]);
                pb[mb][1] = packres(pa[mb][1], s[mb][2 * ks2][2],     s[mb][2 * ks2][3]);
                pb[mb][2] = packres(pa[mb][2], s[mb][2 * ks2 + 1][0], s[mb][2 * ks2 + 1][1]);
                pb[mb][3] = packres(pa[mb][3], s[mb][2 * ks2 + 1][2], s[mb][2 * ks2 + 1][3]);
            }

            uint32_t row = ks2 * 16 + lr;
            uint32_t rb = st + 2 * AKT + row * 128;
            uint32_t key = row & 7;
#pragma unroll
            for (int dg = 0; dg < 4; dg++) {
                uint32_t ch = dg * 2 + lc;
                uint32_t a = rb + ((ch ^ key) << 4);
                uint32_t v0, v1, v2, v3, w0, w1, w2, w3;
                ldm4t(a, v0, v1, v2, v3);
                ldm4t(a + AKT, w0, w1, w2, w3);
#pragma unroll
                for (int mb = 0; mb < 2; mb++) {
                    mma_bf16(o[mb][2 * dg],     pa[mb], v0, v1);
                    mma_bf16(o[mb][2 * dg],     pb[mb], v0, v1);
                    mma_bf16(o[mb][2 * dg],     pa[mb], w0, w1);
                    mma_bf16(o[mb][2 * dg + 1], pa[mb], v2, v3);
                    mma_bf16(o[mb][2 * dg + 1], pb[mb], v2, v3);
                    mma_bf16(o[mb][2 * dg + 1], pa[mb], w2, w3);
                }
            }
        }
    }

    // ---- epilogue: normalize, write bf16 hi/lo [b,t,C] ----
#pragma unroll
    for (int mb = 0; mb < 2; mb++) {
        const float i0 = 1.0f / l[mb][0], i1 = 1.0f / l[mb][1];
        const int row = q0 + warp * 32 + mb * 16 + (lane >> 2);
        const size_t ob = ((size_t)b * T_DIM + row) * C_DIM + h * 64 + (lane & 3) * 2;
#pragma unroll
        for (int dnt = 0; dnt < 8; dnt++) {
            float v0 = o[mb][dnt][0] * i0, v1 = o[mb][dnt][1] * i0;
            uint32_t hp = packbf(v0, v1);
            *(uint32_t*)(ah_ + ob + dnt * 8) = hp;
            *(uint32_t*)(al_ + ob + dnt * 8) = packres(hp, v0, v1);
            float u0 = o[mb][dnt][2] * i1, u1 = o[mb][dnt][3] * i1;
            uint32_t hq = packbf(u0, u1);
            *(uint32_t*)(ah_ + ob + 8 * C_DIM + dnt * 8) = hq;
            *(uint32_t*)(al_ + ob + 8 * C_DIM + dnt * 8) = packres(hq, u0, u1);
        }
    }
}

// ---------------------------------------------------------------------------
// launch
// ---------------------------------------------------------------------------
extern "C" void kernel_launch(void* const* d_in, const int* in_sizes, int n_in,
                              void* d_out, int out_size)
{
    const float* x    = (const float*)d_in[0];
    const float* wqkv = (const float*)d_in[1];
    const float* wout = (const float*)d_in[2];
    float* out = (float*)d_out;

    __nv_bfloat16 *xh, *xl, *wqh, *wql, *woh, *wol, *ah, *al;
    __nv_bfloat16 *qh2, *ql2, *kh2, *kl2, *vh2, *vl2;
    cudaGetSymbolAddress((void**)&xh, g_xh);
    cudaGetSymbolAddress((void**)&xl, g_xl);
    cudaGetSymbolAddress((void**)&wqh, g_wqh);
    cudaGetSymbolAddress((void**)&wql, g_wql);
    cudaGetSymbolAddress((void**)&woh, g_woh);
    cudaGetSymbolAddress((void**)&wol, g_wol);
    cudaGetSymbolAddress((void**)&ah, g_ah);
    cudaGetSymbolAddress((void**)&al, g_al);
    cudaGetSymbolAddress((void**)&qh2, g_qh2);
    cudaGetSymbolAddress((void**)&ql2, g_ql2);
    cudaGetSymbolAddress((void**)&kh2, g_kh2);
    cudaGetSymbolAddress((void**)&kl2, g_kl2);
    cudaGetSymbolAddress((void**)&vh2, g_vh2);
    cudaGetSymbolAddress((void**)&vl2, g_vl2);

    const int gemm_smem = GNSTAGE * GSTAGE;     // 98304
    cudaFuncSetAttribute(gemm_bf16x3<0>, cudaFuncAttributeMaxDynamicSharedMemorySize,
                         gemm_smem);
    cudaFuncSetAttribute(gemm_bf16x3<1>, cudaFuncAttributeMaxDynamicSharedMemorySize,
                         gemm_smem);
    const int attn_smem = ASOFF + 2 * AST;      // 98304
    cudaFuncSetAttribute(attn_mma, cudaFuncAttributeMaxDynamicSharedMemorySize,
                         attn_smem);

    {
        int n4 = MROWS * KDIM / 4;
        split_bf16<<<(n4 + 255) / 256, 256>>>((const float4*)x,
            (uint32_t*)xh, (uint32_t*)xl, n4);
        n4 = 3 * C_DIM * KDIM / 4;
        split_bf16<<<(n4 + 255) / 256, 256>>>((const float4*)wqkv,
            (uint32_t*)wqh, (uint32_t*)wql, n4);
        n4 = C_DIM * KDIM / 4;
        split_bf16<<<(n4 + 255) / 256, 256>>>((const float4*)wout,
            (uint32_t*)woh, (uint32_t*)wol, n4);
    }

    // 1) QKV projection, fused split epilogue -> q/k/v hi/lo [b,h,t,d]
    gemm_bf16x3<1><<<dim3(3 * C_DIM / 128, MROWS / 128), 128, gemm_smem>>>(
        xh, xl, wqh, wql, nullptr,
        qh2, ql2, kh2, kl2, vh2, vl2, 3 * C_DIM, KDIM);

    // 2) flash attention (tensor-core), writes bf16 hi/lo att
    attn_mma<<<dim3(T_DIM / 128, H_DIM, B_DIM), 128, attn_smem>>>(
        qh2, ql2, kh2, kl2, vh2, vl2, ah, al);

    // 3) output projection: [8192, 1024] fp32
    gemm_bf16x3<0><<<dim3(C_DIM / 128, MROWS / 128), 128, gemm_smem>>>(
        ah, al, woh, wol, out,
        nullptr, nullptr, nullptr, nullptr, nullptr, nullptr, C_DIM, KDIM);
}

// round 10
// speedup vs baseline: 2.7342x; 2.5440x over previous
#include <cuda_runtime.h>
#include <cuda_fp16.h>
#include <cstdint>

#define B_DIM 2
#define T_DIM 4096
#define C_DIM 1024
#define H_DIM 16
#define D_DIM 64
#define MROWS (B_DIM * T_DIM)   // 8192
#define KDIM  C_DIM             // 1024

// ---------------- static device scratch (no allocs allowed) ----------------
__device__ __align__(256) __half g_x16[(size_t)MROWS * KDIM];
__device__ __align__(256) __half g_wq16[(size_t)3 * C_DIM * KDIM];
__device__ __align__(256) __half g_wo16[(size_t)C_DIM * KDIM];
__device__ __align__(256) __half g_att16[(size_t)MROWS * C_DIM];
// per-head [b,h,t,d] fp16 (q pre-scaled by 0.125*log2e)
__device__ __align__(256) __half g_q16[(size_t)MROWS * C_DIM];
__device__ __align__(256) __half g_k16[(size_t)MROWS * C_DIM];
__device__ __align__(256) __half g_v16[(size_t)MROWS * C_DIM];

// ---------------------------------------------------------------------------
// PTX helpers
// ---------------------------------------------------------------------------
__device__ __forceinline__ uint32_t cvta_s(const void* p) {
    uint32_t a;
    asm("{ .reg .u64 t; cvta.to.shared.u64 t, %1; cvt.u32.u64 %0, t; }"
        : "=r"(a) : "l"(p));
    return a;
}

__device__ __forceinline__ void cp16(uint32_t dst, const void* src) {
    asm volatile("cp.async.cg.shared.global [%0], [%1], 16;"
                 :: "r"(dst), "l"(src) : "memory");
}

__device__ __forceinline__ void ldm4(uint32_t addr, uint32_t& r0, uint32_t& r1,
                                     uint32_t& r2, uint32_t& r3) {
    asm volatile("ldmatrix.sync.aligned.m8n8.x4.shared.b16 {%0,%1,%2,%3}, [%4];"
                 : "=r"(r0), "=r"(r1), "=r"(r2), "=r"(r3) : "r"(addr));
}

__device__ __forceinline__ void ldm4t(uint32_t addr, uint32_t& r0, uint32_t& r1,
                                      uint32_t& r2, uint32_t& r3) {
    asm volatile("ldmatrix.sync.aligned.m8n8.x4.trans.shared.b16 {%0,%1,%2,%3}, [%4];"
                 : "=r"(r0), "=r"(r1), "=r"(r2), "=r"(r3) : "r"(addr));
}

__device__ __forceinline__ void mma_f16(float* d, const uint32_t* a,
                                        uint32_t b0, uint32_t b1) {
    asm volatile(
        "mma.sync.aligned.m16n8k16.row.col.f32.f16.f16.f32 "
        "{%0,%1,%2,%3}, {%4,%5,%6,%7}, {%8,%9}, {%0,%1,%2,%3};"
        : "+f"(d[0]), "+f"(d[1]), "+f"(d[2]), "+f"(d[3])
        : "r"(a[0]), "r"(a[1]), "r"(a[2]), "r"(a[3]), "r"(b0), "r"(b1));
}

__device__ __forceinline__ float ex2f(float x) {
    float y;
    asm("ex2.approx.f32 %0, %1;" : "=f"(y) : "f"(x));
    return y;
}

// pack {lo, hi} floats into f16x2 (lo in low half)
__device__ __forceinline__ uint32_t pack16(float lo, float hi) {
    uint32_t r;
    asm("cvt.rn.f16x2.f32 %0, %1, %2;" : "=r"(r) : "f"(hi), "f"(lo));
    return r;
}

// SW128: row r (128B rows), 16B chunk c(0..7) -> byte offset
__device__ __forceinline__ uint32_t swz(uint32_t r, uint32_t c) {
    return r * 128 + ((c ^ (r & 7)) << 4);
}

// ---------------------------------------------------------------------------
// convert fp32 -> fp16
// ---------------------------------------------------------------------------
__global__ __launch_bounds__(256) void cvt_fp16(
    const float4* __restrict__ in, uint32_t* __restrict__ out, int n4)
{
    int i = blockIdx.x * blockDim.x + threadIdx.x;
    if (i >= n4) return;
    float4 v = in[i];
    out[2 * i]     = pack16(v.x, v.y);
    out[2 * i + 1] = pack16(v.z, v.w);
}

// ---------------------------------------------------------------------------
// fp16 GEMM: C[M,N] = A[M,K] @ B[N,K]^T, fp32 accum.
// CTA 128x128, 4 warps (64x64 each), BK=64, SW128 smem, 3-stage, 2 CTAs/SM.
// MODE 0: write fp32 C.   MODE 1: write fp16 q(scaled)/k/v in [b,h,t,d].
// ---------------------------------------------------------------------------
#define GTILE   16384       // 128 rows x 64 fp16 cols (128B rows)
#define GSTAGE  32768       // A + B
#define GNSTAGE 3

__device__ __forceinline__ void g_ldtile(
    const __half* __restrict__ G, int K, int row0, int k0,
    uint32_t base, int tid)
{
#pragma unroll
    for (int t = 0; t < 8; t++) {
        int idx = tid + t * 128;           // 0..1023
        int r = idx >> 3, c = idx & 7;
        cp16(base + swz(r, c), G + (size_t)(row0 + r) * K + k0 + c * 8);
    }
}

#define QSCALE 0.180336880f   // 0.125 * log2(e)

template <int MODE>
__global__ __launch_bounds__(128, 2) void gemm_f16(
    const __half* __restrict__ A, const __half* __restrict__ B,
    float* __restrict__ C,
    __half* __restrict__ q16, __half* __restrict__ k16,
    __half* __restrict__ v16, int N, int K)
{
    extern __shared__ __align__(128) char smraw[];
    const uint32_t smbase = cvta_s(smraw);

    const int tid  = threadIdx.x;
    const int wid  = tid >> 5;
    const int lane = tid & 31;
    const int n0 = blockIdx.x * 128;
    const int m0 = blockIdx.y * 128;
    const int wm = (wid & 1) * 64;
    const int wn = (wid >> 1) * 64;
    const int lr = lane & 15;
    const int lc = lane >> 4;

    float acc[4][8][4];
#pragma unroll
    for (int i = 0; i < 4; i++)
#pragma unroll
        for (int j = 0; j < 8; j++)
#pragma unroll
            for (int k = 0; k < 4; k++) acc[i][j][k] = 0.0f;

    const int nch = K / 64;   // 16

#pragma unroll
    for (int c = 0; c < 2; c++) {
        uint32_t sb = smbase + c * GSTAGE;
        g_ldtile(A, K, m0, c * 64, sb, tid);
        g_ldtile(B, K, n0, c * 64, sb + GTILE, tid);
        asm volatile("cp.async.commit_group;" ::: "memory");
    }

    for (int c = 0; c < nch; c++) {
        if (c + 1 < nch)
            asm volatile("cp.async.wait_group 1;" ::: "memory");
        else
            asm volatile("cp.async.wait_group 0;" ::: "memory");
        __syncthreads();

        if (c + 2 < nch) {
            uint32_t db = smbase + ((c + 2) % GNSTAGE) * GSTAGE;
            int kk = (c + 2) * 64;
            g_ldtile(A, K, m0, kk, db, tid);
            g_ldtile(B, K, n0, kk, db + GTILE, tid);
            asm volatile("cp.async.commit_group;" ::: "memory");
        }

        uint32_t sb = smbase + (c % GNSTAGE) * GSTAGE;

#pragma unroll
        for (int ks = 0; ks < 4; ks++) {
            const uint32_t ch = ks * 2 + lc;
            uint32_t af[4][4];
#pragma unroll
            for (int mt = 0; mt < 4; mt++) {
                uint32_t row = wm + mt * 16 + lr;
                ldm4(sb + row * 128 + ((ch ^ (row & 7)) << 4),
                     af[mt][0], af[mt][1], af[mt][2], af[mt][3]);
            }
            uint32_t bf[4][4];
#pragma unroll
            for (int p = 0; p < 4; p++) {
                uint32_t row = wn + p * 16 + lr;
                ldm4(sb + GTILE + row * 128 + ((ch ^ (row & 7)) << 4),
                     bf[p][0], bf[p][1], bf[p][2], bf[p][3]);
            }
#pragma unroll
            for (int mt = 0; mt < 4; mt++) {
#pragma unroll
                for (int nt = 0; nt < 8; nt++) {
                    const int p = nt >> 1, h = nt & 1;
                    mma_f16(acc[mt][nt], af[mt], bf[p][h], bf[p][2 + h]);
                }
            }
        }
    }

    const int er = lane >> 2;
    const int ec = (lane & 3) * 2;
#pragma unroll
    for (int mt = 0; mt < 4; mt++) {
#pragma unroll
        for (int nt = 0; nt < 8; nt++) {
            if (MODE == 0) {
                size_t row = (size_t)(m0 + wm + mt * 16 + er);
                int col = n0 + wn + nt * 8 + ec;
                *(float2*)(C + row * N + col) =
                    make_float2(acc[mt][nt][0], acc[mt][nt][1]);
                *(float2*)(C + (row + 8) * N + col) =
                    make_float2(acc[mt][nt][2], acc[mt][nt][3]);
            } else {
                int col = n0 + wn + nt * 8 + ec;       // 0..3071
                int type = col >> 10;
                int hh = (col >> 6) & 15;
                int d = col & 63;
                __half* dst = (type == 0) ? q16 : (type == 1) ? k16 : v16;
                float sc = (type == 0) ? QSCALE : 1.0f;
#pragma unroll
                for (int rr = 0; rr < 2; rr++) {
                    int row = m0 + wm + mt * 16 + er + rr * 8;
                    int bb = row >> 12, tt = row & 4095;
                    size_t o = ((size_t)(bb * H_DIM + hh) * T_DIM + tt) * 64 + d;
                    *(uint32_t*)(dst + o) =
                        pack16(acc[mt][nt][2 * rr] * sc,
                               acc[mt][nt][2 * rr + 1] * sc);
                }
            }
        }
    }
}

// ---------------------------------------------------------------------------
// Flash attention, fp16 single-term, causal.
// Br=128 (4 warps x 32 rows), Bc=64, SW128 smem, 2-stage, 48KB, 2 CTAs/SM.
// q pre-scaled by 0.125*log2e -> scores already in log2 units.
// ---------------------------------------------------------------------------
#define AQT 16384            // Q tile 128x64 fp16
#define AKT 8192             // K or V tile 64x64 fp16
#define AST 16384            // stage = K + V
#define ASOFF 16384

__device__ __forceinline__ void kload(
    const __half* __restrict__ k16, const __half* __restrict__ v16,
    size_t gbase, uint32_t st, int tid)
{
#pragma unroll
    for (int t = 0; t < 8; t++) {
        int idx = tid + t * 128;            // 0..1023
        int tile = idx >> 9;                // 0=K 1=V
        int rem = idx & 511;
        int r = rem >> 3, c = rem & 7;
        cp16(st + tile * AKT + swz(r, c),
             (tile ? v16 : k16) + gbase + (size_t)r * 64 + c * 8);
    }
}

__global__ __launch_bounds__(128, 2) void attn_f16(
    const __half* __restrict__ q16, const __half* __restrict__ k16,
    const __half* __restrict__ v16, __half* __restrict__ att16)
{
    extern __shared__ __align__(128) char smraw2[];
    const uint32_t sb = cvta_s(smraw2);
    const int qt = gridDim.x - 1 - blockIdx.x;   // heavy tiles first
    const int h = blockIdx.y, b = blockIdx.z;
    const int tid = threadIdx.x, warp = tid >> 5, lane = tid & 31;
    const int q0 = qt * 128;
    const size_t head = (size_t)(b * H_DIM + h) * T_DIM;
    const int nkt = 2 * qt + 2;
    const int lr = lane & 15, lc = lane >> 4;

    // ---- prologue: Q + stage0 ----
    {
        size_t g = (head + q0) * 64;
#pragma unroll
        for (int t = 0; t < 8; t++) {
            int idx = tid + t * 128;        // 0..1023
            int r = idx >> 3, c = idx & 7;
            cp16(sb + swz(r, c), q16 + g + (size_t)r * 64 + c * 8);
        }
        kload(k16, v16, head * 64, sb + ASOFF, tid);
        asm volatile("cp.async.commit_group;" ::: "memory");
        asm volatile("cp.async.wait_group 0;" ::: "memory");
    }
    __syncthreads();

    // ---- Q fragments, resident (2 m-blocks x 4 ks) ----
    uint32_t qf[2][4][4];
#pragma unroll
    for (int mb = 0; mb < 2; mb++) {
        uint32_t row = warp * 32 + mb * 16 + lr;
        uint32_t rb = sb + row * 128;
        uint32_t key = row & 7;
#pragma unroll
        for (int ks = 0; ks < 4; ks++) {
            uint32_t ch = ks * 2 + lc;
            ldm4(rb + ((ch ^ key) << 4),
                 qf[mb][ks][0], qf[mb][ks][1], qf[mb][ks][2], qf[mb][ks][3]);
        }
    }

    float m[2][2], l[2][2];
#pragma unroll
    for (int mb = 0; mb < 2; mb++) {
        m[mb][0] = -1e30f; m[mb][1] = -1e30f;
        l[mb][0] = 0.0f;   l[mb][1] = 0.0f;
    }
    float o[2][8][4];
#pragma unroll
    for (int mb = 0; mb < 2; mb++)
#pragma unroll
        for (int i = 0; i < 8; i++)
#pragma unroll
            for (int j = 0; j < 4; j++) o[mb][i][j] = 0.0f;

    const int grow = q0 + warp * 32;

    for (int kt = 0; kt < nkt; kt++) {
        if (kt > 0) {
            asm volatile("cp.async.wait_group 0;" ::: "memory");
            __syncthreads();
        }
        if (kt + 1 < nkt) {
            kload(k16, v16, (head + (size_t)(kt + 1) * 64) * 64,
                  sb + ASOFF + ((kt + 1) & 1) * AST, tid);
            asm volatile("cp.async.commit_group;" ::: "memory");
        }
        const uint32_t st = sb + ASOFF + (kt & 1) * AST;

        // ---- S = Q K^T ----
        float s[2][8][4];
#pragma unroll
        for (int mb = 0; mb < 2; mb++)
#pragma unroll
            for (int i = 0; i < 8; i++)
#pragma unroll
                for (int j = 0; j < 4; j++) s[mb][i][j] = 0.0f;

#pragma unroll
        for (int ks = 0; ks < 4; ks++) {
            uint32_t ch = ks * 2 + lc;
#pragma unroll
            for (int ng = 0; ng < 4; ng++) {
                uint32_t row = ng * 16 + lr;
                uint32_t h0, h1, h2, h3;
                ldm4(st + row * 128 + ((ch ^ (row & 7)) << 4), h0, h1, h2, h3);
#pragma unroll
                for (int mb = 0; mb < 2; mb++) {
                    mma_f16(s[mb][2 * ng],     qf[mb][ks], h0, h2);
                    mma_f16(s[mb][2 * ng + 1], qf[mb][ks], h1, h3);
                }
            }
        }

        // ---- causal mask ----
        if (kt * 64 + 63 > grow) {
            const int cb = kt * 64 + (lane & 3) * 2;
#pragma unroll
            for (int mb = 0; mb < 2; mb++) {
                const int rb0 = grow + mb * 16 + (lane >> 2);
#pragma unroll
                for (int nt = 0; nt < 8; nt++) {
                    int c0 = cb + nt * 8;
                    if (c0     > rb0)     s[mb][nt][0] = -1e30f;
                    if (c0 + 1 > rb0)     s[mb][nt][1] = -1e30f;
                    if (c0     > rb0 + 8) s[mb][nt][2] = -1e30f;
                    if (c0 + 1 > rb0 + 8) s[mb][nt][3] = -1e30f;
                }
            }
        }

        // ---- online softmax (scores already in log2 units) ----
#pragma unroll
        for (int mb = 0; mb < 2; mb++) {
            float mx0 = s[mb][0][0], mx1 = s[mb][0][2];
#pragma unroll
            for (int nt = 0; nt < 8; nt++) {
                mx0 = fmaxf(mx0, fmaxf(s[mb][nt][0], s[mb][nt][1]));
                mx1 = fmaxf(mx1, fmaxf(s[mb][nt][2], s[mb][nt][3]));
            }
            mx0 = fmaxf(mx0, __shfl_xor_sync(0xffffffffu, mx0, 1));
            mx0 = fmaxf(mx0, __shfl_xor_sync(0xffffffffu, mx0, 2));
            mx1 = fmaxf(mx1, __shfl_xor_sync(0xffffffffu, mx1, 1));
            mx1 = fmaxf(mx1, __shfl_xor_sync(0xffffffffu, mx1, 2));

            float mn0 = fmaxf(m[mb][0], mx0), mn1 = fmaxf(m[mb][1], mx1);
            float a0 = ex2f(m[mb][0] - mn0);
            float a1 = ex2f(m[mb][1] - mn1);
            m[mb][0] = mn0; m[mb][1] = mn1;

            float rs0 = 0.0f, rs1 = 0.0f;
#pragma unroll
            for (int nt = 0; nt < 8; nt++) {
                s[mb][nt][0] = ex2f(s[mb][nt][0] - mn0);
                s[mb][nt][1] = ex2f(s[mb][nt][1] - mn0);
                s[mb][nt][2] = ex2f(s[mb][nt][2] - mn1);
                s[mb][nt][3] = ex2f(s[mb][nt][3] - mn1);
                rs0 += s[mb][nt][0] + s[mb][nt][1];
                rs1 += s[mb][nt][2] + s[mb][nt][3];
            }
            rs0 += __shfl_xor_sync(0xffffffffu, rs0, 1);
            rs0 += __shfl_xor_sync(0xffffffffu, rs0, 2);
            rs1 += __shfl_xor_sync(0xffffffffu, rs1, 1);
            rs1 += __shfl_xor_sync(0xffffffffu, rs1, 2);
            l[mb][0] = l[mb][0] * a0 + rs0;
            l[mb][1] = l[mb][1] * a1 + rs1;

#pragma unroll
            for (int i = 0; i < 8; i++) {
                o[mb][i][0] *= a0; o[mb][i][1] *= a0;
                o[mb][i][2] *= a1; o[mb][i][3] *= a1;
            }
        }

        // ---- O += P V ----
#pragma unroll
        for (int ks2 = 0; ks2 < 4; ks2++) {
            uint32_t pa[2][4];
#pragma unroll
            for (int mb = 0; mb < 2; mb++) {
                pa[mb][0] = pack16(s[mb][2 * ks2][0],     s[mb][2 * ks2][1]);
                pa[mb][1] = pack16(s[mb][2 * ks2][2],     s[mb][2 * ks2][3]);
                pa[mb][2] = pack16(s[mb][2 * ks2 + 1][0], s[mb][2 * ks2 + 1][1]);
                pa[mb][3] = pack16(s[mb][2 * ks2 + 1][2], s[mb][2 * ks2 + 1][3]);
            }
            uint32_t row = ks2 * 16 + lr;
            uint32_t rb = st + AKT + row * 128;
            uint32_t key = row & 7;
#pragma unroll
            for (int dg = 0; dg < 4; dg++) {
                uint32_t ch = dg * 2 + lc;
                uint32_t v0, v1, v2, v3;
                ldm4t(rb + ((ch ^ key) << 4), v0, v1, v2, v3);
#pragma unroll
                for (int mb = 0; mb < 2; mb++) {
                    mma_f16(o[mb][2 * dg],     pa[mb], v0, v1);
                    mma_f16(o[mb][2 * dg + 1], pa[mb], v2, v3);
                }
            }
        }
    }

    // ---- epilogue: normalize, write fp16 att [b,t,C] ----
#pragma unroll
    for (int mb = 0; mb < 2; mb++) {
        const float i0 = 1.0f / l[mb][0], i1 = 1.0f / l[mb][1];
        const int row = q0 + warp * 32 + mb * 16 + (lane >> 2);
        const size_t ob = ((size_t)b * T_DIM + row) * C_DIM + h * 64 + (lane & 3) * 2;
#pragma unroll
        for (int dnt = 0; dnt < 8; dnt++) {
            *(uint32_t*)(att16 + ob + dnt * 8) =
                pack16(o[mb][dnt][0] * i0, o[mb][dnt][1] * i0);
            *(uint32_t*)(att16 + ob + 8 * C_DIM + dnt * 8) =
                pack16(o[mb][dnt][2] * i1, o[mb][dnt][3] * i1);
        }
    }
}

// ---------------------------------------------------------------------------
// launch
// ---------------------------------------------------------------------------
extern "C" void kernel_launch(void* const* d_in, const int* in_sizes, int n_in,
                              void* d_out, int out_size)
{
    const float* x    = (const float*)d_in[0];
    const float* wqkv = (const float*)d_in[1];
    const float* wout = (const float*)d_in[2];
    float* out = (float*)d_out;

    __half *x16, *wq16, *wo16, *att16, *q16, *k16, *v16;
    cudaGetSymbolAddress((void**)&x16, g_x16);
    cudaGetSymbolAddress((void**)&wq16, g_wq16);
    cudaGetSymbolAddress((void**)&wo16, g_wo16);
    cudaGetSymbolAddress((void**)&att16, g_att16);
    cudaGetSymbolAddress((void**)&q16, g_q16);
    cudaGetSymbolAddress((void**)&k16, g_k16);
    cudaGetSymbolAddress((void**)&v16, g_v16);

    const int gemm_smem = GNSTAGE * GSTAGE;     // 98304
    cudaFuncSetAttribute(gemm_f16<0>, cudaFuncAttributeMaxDynamicSharedMemorySize,
                         gemm_smem);
    cudaFuncSetAttribute(gemm_f16<1>, cudaFuncAttributeMaxDynamicSharedMemorySize,
                         gemm_smem);
    const int attn_smem = ASOFF + 2 * AST;      // 49152
    cudaFuncSetAttribute(attn_f16, cudaFuncAttributeMaxDynamicSharedMemorySize,
                         attn_smem);

    // convert inputs to fp16
    {
        int n4 = MROWS * KDIM / 4;
        cvt_fp16<<<(n4 + 255) / 256, 256>>>((const float4*)x, (uint32_t*)x16, n4);
        n4 = 3 * C_DIM * KDIM / 4;
        cvt_fp16<<<(n4 + 255) / 256, 256>>>((const float4*)wqkv, (uint32_t*)wq16, n4);
        n4 = C_DIM * KDIM / 4;
        cvt_fp16<<<(n4 + 255) / 256, 256>>>((const float4*)wout, (uint32_t*)wo16, n4);
    }

    // 1) QKV projection, fused epilogue -> q(scaled)/k/v fp16 [b,h,t,d]
    gemm_f16<1><<<dim3(3 * C_DIM / 128, MROWS / 128), 128, gemm_smem>>>(
        x16, wq16, nullptr, q16, k16, v16, 3 * C_DIM, KDIM);

    // 2) flash attention (fp16 tensor-core), writes fp16 att
    attn_f16<<<dim3(T_DIM / 128, H_DIM, B_DIM), 128, attn_smem>>>(
        q16, k16, v16, att16);

    // 3) output projection: [8192, 1024] fp32
    gemm_f16<0><<<dim3(C_DIM / 128, MROWS / 128), 128, gemm_smem>>>(
        att16, wo16, out, nullptr, nullptr, nullptr, C_DIM, KDIM);
}